// round 3
// baseline (speedup 1.0000x reference)
#include <cuda_runtime.h>
#include <cuda_bf16.h>

// ---------------- problem constants ----------------
#define BATCH   8
#define DMODEL  256
#define NH      8
#define NLVL    4
#define NPT     4
#define DH      32
#define NLAYERS 6
#define DFF     1024
#define LQ      5440            // 4096 + 1024 + 256 + 64
#define MROWS   (BATCH * LQ)    // 43520

// ---------------- scratch (device globals; no allocation allowed) ----------------
__device__ float g_x   [MROWS * DMODEL];
__device__ float g_pos [MROWS * DMODEL];
__device__ float g_q   [MROWS * DMODEL];
__device__ float g_val [MROWS * DMODEL];
__device__ float g_off [MROWS * 256];
__device__ float g_attn[MROWS * 128];
__device__ float g_acc [MROWS * DMODEL];
__device__ float g_tmp [MROWS * DMODEL];
__device__ float g_h   [MROWS * DFF];

// ---------------- helpers ----------------
__device__ __forceinline__ float warp_sum(float v) {
#pragma unroll
    for (int o = 16; o > 0; o >>= 1) v += __shfl_xor_sync(0xffffffffu, v, o);
    return v;
}
// reduce within each 16-lane half (halves hold identical data)
__device__ __forceinline__ float half_sum16(float v) {
#pragma unroll
    for (int o = 8; o > 0; o >>= 1) v += __shfl_xor_sync(0xffffffffu, v, o);
    return v;
}
__device__ __forceinline__ float half_max16(float v) {
#pragma unroll
    for (int o = 8; o > 0; o >>= 1) v = fmaxf(v, __shfl_xor_sync(0xffffffffu, v, o));
    return v;
}

// ---------------- flatten: (B,D,H,W) -> (B,LQ,D), plus pos + level_enc ----------------
// grid: (170 q-tiles, 8 d-tiles, B), block (32, 32)
__global__ void flatten_kernel(const float* __restrict__ s0, const float* __restrict__ s1,
                               const float* __restrict__ s2, const float* __restrict__ s3,
                               const float* __restrict__ p0, const float* __restrict__ p1,
                               const float* __restrict__ p2, const float* __restrict__ p3,
                               const float* __restrict__ lenc,
                               float* __restrict__ x, float* __restrict__ pos)
{
    __shared__ float ts[32][33];
    __shared__ float tp[32][33];
    const int b  = blockIdx.z;
    const int q0 = blockIdx.x * 32;
    const int d0 = blockIdx.y * 32;

    int l, start, HW;
    const float *src, *pp;
    if (q0 < 4096)      { l = 0; start = 0;    HW = 4096; src = s0; pp = p0; }
    else if (q0 < 5120) { l = 1; start = 4096; HW = 1024; src = s1; pp = p1; }
    else if (q0 < 5376) { l = 2; start = 5120; HW = 256;  src = s2; pp = p2; }
    else                { l = 3; start = 5376; HW = 64;   src = s3; pp = p3; }

    const int pix0 = q0 - start;
    const int tx = threadIdx.x, ty = threadIdx.y;

    long sidx = ((long)b * DMODEL + (d0 + ty)) * HW + pix0 + tx;
    ts[ty][tx] = src[sidx];
    tp[ty][tx] = pp[sidx];
    __syncthreads();

    const int q  = q0 + ty;
    const int dd = d0 + tx;
    long oidx = ((long)b * LQ + q) * DMODEL + dd;
    x[oidx]   = ts[tx][ty];
    pos[oidx] = tp[tx][ty] + lenc[l * DMODEL + dd];
}

// ---------------- tiled fp32 GEMM: C[M,N] = A[M,K] @ B[K,N] + bias, optional relu ----------
// BM=BN=128, BK=16, 256 threads, 8x8 microtile per thread
__global__ void __launch_bounds__(256) gemm_kernel(
    const float* __restrict__ A, const float* __restrict__ B,
    const float* __restrict__ bias, float* __restrict__ C,
    int M, int N, int K, int relu)
{
    __shared__ float As[16][128];
    __shared__ float Bs[16][128];

    const int bm0 = blockIdx.y * 128;
    const int bn0 = blockIdx.x * 128;
    const int tid = threadIdx.x;
    const int tx = tid % 16, ty = tid / 16;

    float acc[8][8];
#pragma unroll
    for (int i = 0; i < 8; i++)
#pragma unroll
        for (int j = 0; j < 8; j++) acc[i][j] = 0.f;

    const int ar = tid >> 2;          // 0..63
    const int ac = (tid & 3) * 4;     // 0,4,8,12
    const int br = tid >> 5;          // 0..7
    const int bc = (tid & 31) * 4;    // 0..124

    for (int k0 = 0; k0 < K; k0 += 16) {
#pragma unroll
        for (int i = 0; i < 2; i++) {
            int r = ar + i * 64;
            float4 v = *(const float4*)(A + (long)(bm0 + r) * K + k0 + ac);
            As[ac + 0][r] = v.x; As[ac + 1][r] = v.y;
            As[ac + 2][r] = v.z; As[ac + 3][r] = v.w;
        }
#pragma unroll
        for (int i = 0; i < 2; i++) {
            int r = br + i * 8;
            float4 v = *(const float4*)(B + (long)(k0 + r) * N + bn0 + bc);
            *(float4*)&Bs[r][bc] = v;
        }
        __syncthreads();
#pragma unroll
        for (int kk = 0; kk < 16; kk++) {
            float ra[8], rb[8];
            *(float4*)&ra[0] = *(const float4*)&As[kk][ty * 8];
            *(float4*)&ra[4] = *(const float4*)&As[kk][ty * 8 + 4];
            *(float4*)&rb[0] = *(const float4*)&Bs[kk][tx * 8];
            *(float4*)&rb[4] = *(const float4*)&Bs[kk][tx * 8 + 4];
#pragma unroll
            for (int i = 0; i < 8; i++)
#pragma unroll
                for (int j = 0; j < 8; j++)
                    acc[i][j] = fmaf(ra[i], rb[j], acc[i][j]);
        }
        __syncthreads();
    }

#pragma unroll
    for (int i = 0; i < 8; i++) {
        const int row = bm0 + ty * 8 + i;
#pragma unroll
        for (int j = 0; j < 8; j += 4) {
            const int col = bn0 + tx * 8 + j;
            float4 v;
            v.x = acc[i][j + 0] + bias[col + 0];
            v.y = acc[i][j + 1] + bias[col + 1];
            v.z = acc[i][j + 2] + bias[col + 2];
            v.w = acc[i][j + 3] + bias[col + 3];
            if (relu) {
                v.x = fmaxf(v.x, 0.f); v.y = fmaxf(v.y, 0.f);
                v.z = fmaxf(v.z, 0.f); v.w = fmaxf(v.w, 0.f);
            }
            *(float4*)(C + (long)row * N + col) = v;
        }
    }
}

// ---------------- elementwise q = x + pos ----------------
__global__ void add_kernel(const float* __restrict__ a, const float* __restrict__ b,
                           float* __restrict__ c, int n4)
{
    int i = blockIdx.x * blockDim.x + threadIdx.x;
    if (i >= n4) return;
    float4 va = ((const float4*)a)[i];
    float4 vb = ((const float4*)b)[i];
    va.x += vb.x; va.y += vb.y; va.z += vb.z; va.w += vb.w;
    ((float4*)c)[i] = va;
}

// ---------------- deformable sampling + fused softmax ----------------
// one warp per (b, q, h); lane = channel d (DH == 32)
// per (b,q,h): 16 samples (NL*NP), 32 offset floats, 16 logits
__global__ void __launch_bounds__(256) sample_kernel(
    const float* __restrict__ val, const float* __restrict__ off,
    const float* __restrict__ logits, float* __restrict__ acc)
{
    const int gwid = (blockIdx.x * blockDim.x + threadIdx.x) >> 5;
    const int lane = threadIdx.x & 31;
    const int h = gwid % NH;
    const int q = (gwid / NH) % LQ;
    const int b = gwid / (NH * LQ);

    const long rowhead = ((long)(b * LQ + q) * NH + h);

    // fused softmax over 16 logits; lanes 16..31 mirror lanes 0..15
    float lv = logits[rowhead * 16 + (lane & 15)];
    float mx = half_max16(lv);
    float e  = __expf(lv - mx);
    float s  = half_sum16(e);
    float wgt = e / s;   // lane (mod 16)'s sample weight

    // reference point from this query's own level/pixel
    int W0, start0;
    if (q < 4096)      { W0 = 64; start0 = 0;    }
    else if (q < 5120) { W0 = 32; start0 = 4096; }
    else if (q < 5376) { W0 = 16; start0 = 5120; }
    else               { W0 = 8;  start0 = 5376; }
    const int pix = q - start0;
    const float refx = ((pix % W0) + 0.5f) / (float)W0;
    const float refy = ((pix / W0) + 0.5f) / (float)W0;   // square levels: H == W

    const float* ob = off + rowhead * 32;   // (NL, NP, 2) = 32 floats
    const int Ls[4] = {64, 32, 16, 8};
    const int Ss[4] = {0, 4096, 5120, 5376};
    float a = 0.f;

#pragma unroll
    for (int l = 0; l < NLVL; l++) {
        const int   HH = Ls[l];
        const float fH = (float)HH;
        const float* vb = val + (((long)b * LQ + Ss[l]) * NH + h) * DH + lane;
#pragma unroll
        for (int p = 0; p < NPT; p++) {
            const int si = l * NPT + p;
            const float ox = ob[si * 2];       // uniform across warp -> broadcast
            const float oy = ob[si * 2 + 1];
            const float aw = __shfl_sync(0xffffffffu, wgt, si);
            const float xx = refx * fH + ox - 0.5f;
            const float yy = refy * fH + oy - 0.5f;
            const float xf = floorf(xx), yf = floorf(yy);
            const int   x0 = (int)xf, y0 = (int)yf;
            const float dx = xx - xf, dy = yy - yf;
            float sv = 0.f;
#pragma unroll
            for (int t = 0; t < 4; t++) {
                const int   xi = x0 + (t & 1);
                const int   yi = y0 + (t >> 1);
                const float wt = ((t & 1) ? dx : 1.f - dx) * ((t >> 1) ? dy : 1.f - dy);
                if (xi >= 0 && xi < HH && yi >= 0 && yi < HH && wt != 0.f)
                    sv += wt * vb[(long)(yi * HH + xi) * (NH * DH)];
            }
            a += aw * sv;
        }
    }
    acc[rowhead * DH + lane] = a;
}

// ---------------- fused residual-add + LayerNorm ----------------
// one warp per row of 256; 8 elems per lane
__global__ void __launch_bounds__(256) add_ln_kernel(
    const float* __restrict__ x, const float* __restrict__ r,
    const float* __restrict__ g, const float* __restrict__ bta,
    float* __restrict__ out)
{
    const int row  = blockIdx.x * 8 + (threadIdx.x >> 5);
    const int lane = threadIdx.x & 31;
    const float* xr = x + (long)row * DMODEL;
    const float* rr = r + (long)row * DMODEL;

    float v[8];
    float sum = 0.f;
#pragma unroll
    for (int k = 0; k < 8; k++) {
        v[k] = xr[lane + 32 * k] + rr[lane + 32 * k];
        sum += v[k];
    }
    sum = warp_sum(sum);
    const float mu = sum * (1.f / 256.f);
    float vs = 0.f;
#pragma unroll
    for (int k = 0; k < 8; k++) { float d = v[k] - mu; vs += d * d; }
    vs = warp_sum(vs) * (1.f / 256.f);
    const float inv = rsqrtf(vs + 1e-5f);
#pragma unroll
    for (int k = 0; k < 8; k++) {
        const int c = lane + 32 * k;
        out[(long)row * DMODEL + c] = (v[k] - mu) * inv * g[c] + bta[c];
    }
}

// ---------------- launch orchestration ----------------
static inline void launch_gemm(const float* A, const float* B, const float* bias,
                               float* C, int M, int N, int K, int relu)
{
    dim3 grid(N / 128, M / 128);
    gemm_kernel<<<grid, 256>>>(A, B, bias, C, M, N, K, relu);
}

extern "C" void kernel_launch(void* const* d_in, const int* in_sizes, int n_in,
                              void* d_out, int out_size)
{
    // Input order: setup_inputs() inserts src{i}, pos{i} INTERLEAVED
    // (src0,pos0,src1,pos1,...). Reference signature lists src0..3 then
    // pos0..3. Disambiguate by size: src0 and pos0 are both 8.4M elems,
    // src1 is 2.1M. If in_sizes[1] == in_sizes[0], order is interleaved.
    const float* src[4];
    const float* pos[4];
    if (in_sizes[1] == in_sizes[0]) {
        for (int i = 0; i < 4; i++) {
            src[i] = (const float*)d_in[2 * i];
            pos[i] = (const float*)d_in[2 * i + 1];
        }
    } else {
        for (int i = 0; i < 4; i++) {
            src[i] = (const float*)d_in[i];
            pos[i] = (const float*)d_in[4 + i];
        }
    }
    const float* lenc  = (const float*)d_in[8];
    const float* Wv    = (const float*)d_in[9];
    const float* bv    = (const float*)d_in[10];
    const float* Wo    = (const float*)d_in[11];
    const float* bo    = (const float*)d_in[12];
    const float* Wa    = (const float*)d_in[13];
    const float* ba    = (const float*)d_in[14];
    const float* Wout  = (const float*)d_in[15];
    const float* bout  = (const float*)d_in[16];
    const float* ln1g  = (const float*)d_in[17];
    const float* ln1b  = (const float*)d_in[18];
    const float* W1    = (const float*)d_in[19];
    const float* b1    = (const float*)d_in[20];
    const float* W2    = (const float*)d_in[21];
    const float* b2    = (const float*)d_in[22];
    const float* ln2g  = (const float*)d_in[23];
    const float* ln2b  = (const float*)d_in[24];
    float* out = (float*)d_out;

    float *x, *posb, *qb, *vb, *ob, *ab, *accb, *tmpb, *hb;
    cudaGetSymbolAddress((void**)&x,    g_x);
    cudaGetSymbolAddress((void**)&posb, g_pos);
    cudaGetSymbolAddress((void**)&qb,   g_q);
    cudaGetSymbolAddress((void**)&vb,   g_val);
    cudaGetSymbolAddress((void**)&ob,   g_off);
    cudaGetSymbolAddress((void**)&ab,   g_attn);
    cudaGetSymbolAddress((void**)&accb, g_acc);
    cudaGetSymbolAddress((void**)&tmpb, g_tmp);
    cudaGetSymbolAddress((void**)&hb,   g_h);

    const int M = MROWS;

    // flatten inputs
    {
        dim3 grid(LQ / 32, DMODEL / 32, BATCH);
        dim3 blk(32, 32);
        flatten_kernel<<<grid, blk>>>(src[0], src[1], src[2], src[3],
                                      pos[0], pos[1], pos[2], pos[3],
                                      lenc, x, posb);
    }

    const int n4 = M * DMODEL / 4;
    const int add_blocks = (n4 + 255) / 256;
    const int sample_blocks = (M * NH * 32) / 256;   // one warp per (b,q,h)
    const int ln_blocks = M / 8;

    for (int i = 0; i < NLAYERS; i++) {
        const float* Wv_i   = Wv   + (long)i * DMODEL * DMODEL;
        const float* bv_i   = bv   + (long)i * DMODEL;
        const float* Wo_i   = Wo   + (long)i * DMODEL * 256;
        const float* bo_i   = bo   + (long)i * 256;
        const float* Wa_i   = Wa   + (long)i * DMODEL * 128;
        const float* ba_i   = ba   + (long)i * 128;
        const float* Wout_i = Wout + (long)i * DMODEL * DMODEL;
        const float* bout_i = bout + (long)i * DMODEL;
        const float* W1_i   = W1   + (long)i * DMODEL * DFF;
        const float* b1_i   = b1   + (long)i * DFF;
        const float* W2_i   = W2   + (long)i * DFF * DMODEL;
        const float* b2_i   = b2   + (long)i * DMODEL;

        // value = x @ Wv + bv
        launch_gemm(x, Wv_i, bv_i, vb, M, DMODEL, DMODEL, 0);
        // q = x + pos
        add_kernel<<<add_blocks, 256>>>(x, posb, qb, n4);
        // offsets, attn logits
        launch_gemm(qb, Wo_i, bo_i, ob, M, 256, DMODEL, 0);
        launch_gemm(qb, Wa_i, ba_i, ab, M, 128, DMODEL, 0);
        // softmax + deformable sampling
        sample_kernel<<<sample_blocks, 256>>>(vb, ob, ab, accb);
        // output projection
        launch_gemm(accb, Wout_i, bout_i, tmpb, M, DMODEL, DMODEL, 0);
        // x = LN(x + attn_out)
        add_ln_kernel<<<ln_blocks, 256>>>(x, tmpb, ln1g + (long)i * DMODEL,
                                          ln1b + (long)i * DMODEL, x);
        // FFN
        launch_gemm(x, W1_i, b1_i, hb, M, DFF, DMODEL, 1);
        launch_gemm(hb, W2_i, b2_i, tmpb, M, DMODEL, DFF, 0);
        // x = LN(x + ffn_out); last layer writes straight to d_out
        float* dst = (i == NLAYERS - 1) ? out : x;
        add_ln_kernel<<<ln_blocks, 256>>>(x, tmpb, ln2g + (long)i * DMODEL,
                                          ln2b + (long)i * DMODEL, dst);
    }
}

// round 5
// speedup vs baseline: 1.6983x; 1.6983x over previous
#include <cuda_runtime.h>
#include <cuda_bf16.h>
#include <cstdint>

// ---------------- problem constants ----------------
#define BATCH   8
#define DMODEL  256
#define NH      8
#define NLVL    4
#define NPT     4
#define DH      32
#define NLAYERS 6
#define DFF     1024
#define LQ      5440            // 4096 + 1024 + 256 + 64
#define MROWS   (BATCH * LQ)    // 43520

// ---------------- scratch (device globals; no allocation allowed) ----------------
__device__ float g_x   [MROWS * DMODEL];
__device__ float g_pos [MROWS * DMODEL];
__device__ float g_q   [MROWS * DMODEL];
__device__ float g_val [MROWS * DMODEL];
__device__ float g_off [MROWS * 256];
__device__ float g_attn[MROWS * 128];
__device__ float g_acc [MROWS * DMODEL];
__device__ float g_tmp [MROWS * DMODEL];
__device__ float g_h   [MROWS * DFF];

// split-bf16 weights, transposed to [N, K] K-major, hi + lo
__device__ __nv_bfloat16 g_wv_h [NLAYERS * 256 * 256];
__device__ __nv_bfloat16 g_wv_l [NLAYERS * 256 * 256];
__device__ __nv_bfloat16 g_wo_h [NLAYERS * 256 * 256];
__device__ __nv_bfloat16 g_wo_l [NLAYERS * 256 * 256];
__device__ __nv_bfloat16 g_wa_h [NLAYERS * 128 * 256];
__device__ __nv_bfloat16 g_wa_l [NLAYERS * 128 * 256];
__device__ __nv_bfloat16 g_wu_h [NLAYERS * 256 * 256];
__device__ __nv_bfloat16 g_wu_l [NLAYERS * 256 * 256];
__device__ __nv_bfloat16 g_w1_h [NLAYERS * 1024 * 256];
__device__ __nv_bfloat16 g_w1_l [NLAYERS * 1024 * 256];
__device__ __nv_bfloat16 g_w2_h [NLAYERS * 256 * 1024];
__device__ __nv_bfloat16 g_w2_l [NLAYERS * 256 * 1024];

// ---------------- helpers ----------------
__device__ __forceinline__ uint32_t smem_u32(const void* p) {
    uint32_t a;
    asm("{ .reg .u64 t; cvta.to.shared.u64 t, %1; cvt.u32.u64 %0, t; }"
        : "=r"(a) : "l"(p));
    return a;
}
__device__ __forceinline__ void ldm4(uint32_t* r, uint32_t addr) {
    asm volatile("ldmatrix.sync.aligned.m8n8.x4.shared.b16 {%0,%1,%2,%3}, [%4];"
                 : "=r"(r[0]), "=r"(r[1]), "=r"(r[2]), "=r"(r[3]) : "r"(addr));
}
__device__ __forceinline__ void mma16816(float* c, const uint32_t* a,
                                         const uint32_t* b) {
    asm volatile(
        "mma.sync.aligned.m16n8k16.row.col.f32.bf16.bf16.f32 "
        "{%0,%1,%2,%3}, {%4,%5,%6,%7}, {%8,%9}, {%0,%1,%2,%3};"
        : "+f"(c[0]), "+f"(c[1]), "+f"(c[2]), "+f"(c[3])
        : "r"(a[0]), "r"(a[1]), "r"(a[2]), "r"(a[3]), "r"(b[0]), "r"(b[1]));
}
__device__ __forceinline__ uint32_t b2u(__nv_bfloat162 v) {
    return *reinterpret_cast<uint32_t*>(&v);
}

// ---------------- weight transpose + bf16 split: W[K,N] -> Wt_hi/lo[N,K] ---------
__global__ void wsplit_kernel(const float* __restrict__ W,
                              __nv_bfloat16* __restrict__ hi,
                              __nv_bfloat16* __restrict__ lo,
                              int K, int N)
{
    __shared__ float t[32][33];
    const int l = blockIdx.z;
    const float* Wl = W + (size_t)l * K * N;
    const int k0 = blockIdx.y * 32, n0 = blockIdx.x * 32;
    t[threadIdx.y][threadIdx.x] = Wl[(size_t)(k0 + threadIdx.y) * N + n0 + threadIdx.x];
    __syncthreads();
    const float v = t[threadIdx.x][threadIdx.y];
    const __nv_bfloat16 h = __float2bfloat16(v);
    const size_t o = (size_t)l * N * K + (size_t)(n0 + threadIdx.y) * K + k0 + threadIdx.x;
    hi[o] = h;
    lo[o] = __float2bfloat16(v - __bfloat162float(h));
}

// ---------------- mma.sync split-bf16 GEMM ----------------
// C[M,N] = A[M,K](fp32) @ Wt[N,K]^T + bias, optional relu.
// CTA tile 128x128, 8 warps (2x4), warp tile 64x32. BK=32. 3 passes hi/lo.
#define PITCH 80   // bytes per smem row (40 bf16): 16B-aligned, conflict-free
#define SA_H  0
#define SA_L  10240
#define SB_H  20480
#define SB_L  30720

__global__ void __launch_bounds__(256, 2) mma_gemm(
    const float* __restrict__ A,
    const __nv_bfloat16* __restrict__ Bh, const __nv_bfloat16* __restrict__ Bl,
    const float* __restrict__ bias, float* __restrict__ C,
    int K, int N, int relu)
{
    __shared__ __align__(16) uint8_t sm[40960];
    const uint32_t sb = smem_u32(sm);

    const int tid = threadIdx.x;
    const int wid = tid >> 5, lane = tid & 31;
    const int wm = wid >> 2, wn = wid & 3;          // 2 x 4 warp grid
    const int m0 = blockIdx.y * 128, n0 = blockIdx.x * 128;
    const int m0w = wm * 64, n0w = wn * 32;
    const int tlq = lane >> 3, rlq = lane & 7;      // ldmatrix tile/row index

    float acc[4][4][4];
#pragma unroll
    for (int i = 0; i < 4; i++)
#pragma unroll
        for (int j = 0; j < 4; j++)
#pragma unroll
            for (int c = 0; c < 4; c++) acc[i][j][c] = 0.f;

    // staging indices
    const int arow = tid >> 1, ahalf = tid & 1;     // A: row, 16-elem half

    const int nchunk = K >> 5;
    for (int ch = 0; ch < nchunk; ch++) {
        const int k0 = ch << 5;

        // ---- stage A (fp32 -> split bf16 hi/lo) ----
        {
            const float4* ar = (const float4*)(A + (size_t)(m0 + arow) * K + k0 + ahalf * 16);
            const int base = arow * PITCH + ahalf * 32;
#pragma unroll
            for (int j = 0; j < 4; j++) {
                float4 v = ar[j];
                __nv_bfloat162 h01 = __floats2bfloat162_rn(v.x, v.y);
                __nv_bfloat162 h23 = __floats2bfloat162_rn(v.z, v.w);
                __nv_bfloat162 l01 = __floats2bfloat162_rn(
                    v.x - __bfloat162float(h01.x), v.y - __bfloat162float(h01.y));
                __nv_bfloat162 l23 = __floats2bfloat162_rn(
                    v.z - __bfloat162float(h23.x), v.w - __bfloat162float(h23.y));
                *(uint2*)(sm + SA_H + base + j * 8) = make_uint2(b2u(h01), b2u(h23));
                *(uint2*)(sm + SA_L + base + j * 8) = make_uint2(b2u(l01), b2u(l23));
            }
        }
        // ---- stage B (pre-split bf16 hi/lo, [N,K] K-major) ----
#pragma unroll
        for (int i = 0; i < 2; i++) {
            const int c = tid + (i << 8);
            const int row = c >> 2, seg = c & 3;
            const size_t go = (size_t)(n0 + row) * K + k0 + seg * 8;
            *(uint4*)(sm + SB_H + row * PITCH + seg * 16) = *(const uint4*)(Bh + go);
            *(uint4*)(sm + SB_L + row * PITCH + seg * 16) = *(const uint4*)(Bl + go);
        }
        __syncthreads();

        // ---- compute: 2 k-steps of 16 ----
#pragma unroll
        for (int ks = 0; ks < 2; ks++) {
            const int kk = ks * 16;
            uint32_t af[16], bfr[16];

            // A hi fragments (4 m-tiles)
#pragma unroll
            for (int mi = 0; mi < 4; mi++) {
                const int r = m0w + mi * 16 + rlq + ((tlq & 1) << 3);
                const int kc = kk + ((tlq >> 1) << 3);
                ldm4(af + mi * 4, sb + SA_H + r * PITCH + kc * 2);
            }
            // B hi fragments (2 calls, 4 n-tiles)
#pragma unroll
            for (int nj = 0; nj < 2; nj++) {
                const int r = n0w + nj * 16 + rlq + ((tlq >> 1) << 3);
                const int kc = kk + ((tlq & 1) << 3);
                ldm4(bfr + nj * 4, sb + SB_H + r * PITCH + kc * 2);
            }
            // pass 1: Ah * Bh
#pragma unroll
            for (int mi = 0; mi < 4; mi++)
#pragma unroll
                for (int ni = 0; ni < 4; ni++) {
                    uint32_t b2r[2] = {bfr[(ni >> 1) * 4 + (ni & 1) * 2],
                                       bfr[(ni >> 1) * 4 + (ni & 1) * 2 + 1]};
                    mma16816(acc[mi][ni], af + mi * 4, b2r);
                }
            // B lo fragments
#pragma unroll
            for (int nj = 0; nj < 2; nj++) {
                const int r = n0w + nj * 16 + rlq + ((tlq >> 1) << 3);
                const int kc = kk + ((tlq & 1) << 3);
                ldm4(bfr + 8 + nj * 4, sb + SB_L + r * PITCH + kc * 2);
            }
            // pass 2: Ah * Bl
#pragma unroll
            for (int mi = 0; mi < 4; mi++)
#pragma unroll
                for (int ni = 0; ni < 4; ni++) {
                    uint32_t b2r[2] = {bfr[8 + (ni >> 1) * 4 + (ni & 1) * 2],
                                       bfr[8 + (ni >> 1) * 4 + (ni & 1) * 2 + 1]};
                    mma16816(acc[mi][ni], af + mi * 4, b2r);
                }
            // A lo fragments (overwrite af)
#pragma unroll
            for (int mi = 0; mi < 4; mi++) {
                const int r = m0w + mi * 16 + rlq + ((tlq & 1) << 3);
                const int kc = kk + ((tlq >> 1) << 3);
                ldm4(af + mi * 4, sb + SA_L + r * PITCH + kc * 2);
            }
            // pass 3: Al * Bh
#pragma unroll
            for (int mi = 0; mi < 4; mi++)
#pragma unroll
                for (int ni = 0; ni < 4; ni++) {
                    uint32_t b2r[2] = {bfr[(ni >> 1) * 4 + (ni & 1) * 2],
                                       bfr[(ni >> 1) * 4 + (ni & 1) * 2 + 1]};
                    mma16816(acc[mi][ni], af + mi * 4, b2r);
                }
        }
        __syncthreads();
    }

    // ---- epilogue ----
    const int g = lane >> 2, tg = lane & 3;
#pragma unroll
    for (int mi = 0; mi < 4; mi++) {
        const int r0 = m0 + m0w + mi * 16 + g;
#pragma unroll
        for (int ni = 0; ni < 4; ni++) {
            const int col = n0 + n0w + ni * 8 + tg * 2;
            const float b0 = bias[col], b1 = bias[col + 1];
            float2 v0 = make_float2(acc[mi][ni][0] + b0, acc[mi][ni][1] + b1);
            float2 v1 = make_float2(acc[mi][ni][2] + b0, acc[mi][ni][3] + b1);
            if (relu) {
                v0.x = fmaxf(v0.x, 0.f); v0.y = fmaxf(v0.y, 0.f);
                v1.x = fmaxf(v1.x, 0.f); v1.y = fmaxf(v1.y, 0.f);
            }
            *(float2*)(C + (size_t)r0 * N + col) = v0;
            *(float2*)(C + (size_t)(r0 + 8) * N + col) = v1;
        }
    }
}

// ---------------- non-GEMM kernels ----------------
__device__ __forceinline__ float warp_sum(float v) {
#pragma unroll
    for (int o = 16; o > 0; o >>= 1) v += __shfl_xor_sync(0xffffffffu, v, o);
    return v;
}
__device__ __forceinline__ float half_sum16(float v) {
#pragma unroll
    for (int o = 8; o > 0; o >>= 1) v += __shfl_xor_sync(0xffffffffu, v, o);
    return v;
}
__device__ __forceinline__ float half_max16(float v) {
#pragma unroll
    for (int o = 8; o > 0; o >>= 1) v = fmaxf(v, __shfl_xor_sync(0xffffffffu, v, o));
    return v;
}

__global__ void flatten_kernel(const float* __restrict__ s0, const float* __restrict__ s1,
                               const float* __restrict__ s2, const float* __restrict__ s3,
                               const float* __restrict__ p0, const float* __restrict__ p1,
                               const float* __restrict__ p2, const float* __restrict__ p3,
                               const float* __restrict__ lenc,
                               float* __restrict__ x, float* __restrict__ pos)
{
    __shared__ float ts[32][33];
    __shared__ float tp[32][33];
    const int b  = blockIdx.z;
    const int q0 = blockIdx.x * 32;
    const int d0 = blockIdx.y * 32;

    int l, start, HW;
    const float *src, *pp;
    if (q0 < 4096)      { l = 0; start = 0;    HW = 4096; src = s0; pp = p0; }
    else if (q0 < 5120) { l = 1; start = 4096; HW = 1024; src = s1; pp = p1; }
    else if (q0 < 5376) { l = 2; start = 5120; HW = 256;  src = s2; pp = p2; }
    else                { l = 3; start = 5376; HW = 64;   src = s3; pp = p3; }

    const int pix0 = q0 - start;
    const int tx = threadIdx.x, ty = threadIdx.y;

    long sidx = ((long)b * DMODEL + (d0 + ty)) * HW + pix0 + tx;
    ts[ty][tx] = src[sidx];
    tp[ty][tx] = pp[sidx];
    __syncthreads();

    const int q  = q0 + ty;
    const int dd = d0 + tx;
    long oidx = ((long)b * LQ + q) * DMODEL + dd;
    x[oidx]   = ts[tx][ty];
    pos[oidx] = tp[tx][ty] + lenc[l * DMODEL + dd];
}

__global__ void add_kernel(const float* __restrict__ a, const float* __restrict__ b,
                           float* __restrict__ c, int n4)
{
    int i = blockIdx.x * blockDim.x + threadIdx.x;
    if (i >= n4) return;
    float4 va = ((const float4*)a)[i];
    float4 vb = ((const float4*)b)[i];
    va.x += vb.x; va.y += vb.y; va.z += vb.z; va.w += vb.w;
    ((float4*)c)[i] = va;
}

__global__ void __launch_bounds__(256) sample_kernel(
    const float* __restrict__ val, const float* __restrict__ off,
    const float* __restrict__ logits, float* __restrict__ acc)
{
    const int gwid = (blockIdx.x * blockDim.x + threadIdx.x) >> 5;
    const int lane = threadIdx.x & 31;
    const int h = gwid % NH;
    const int q = (gwid / NH) % LQ;
    const int b = gwid / (NH * LQ);

    const long rowhead = ((long)(b * LQ + q) * NH + h);

    float lv = logits[rowhead * 16 + (lane & 15)];
    float mx = half_max16(lv);
    float e  = __expf(lv - mx);
    float s  = half_sum16(e);
    float wgt = e / s;

    int W0, start0;
    if (q < 4096)      { W0 = 64; start0 = 0;    }
    else if (q < 5120) { W0 = 32; start0 = 4096; }
    else if (q < 5376) { W0 = 16; start0 = 5120; }
    else               { W0 = 8;  start0 = 5376; }
    const int pix = q - start0;
    const float refx = ((pix % W0) + 0.5f) / (float)W0;
    const float refy = ((pix / W0) + 0.5f) / (float)W0;

    const float* ob = off + rowhead * 32;
    const int Ls[4] = {64, 32, 16, 8};
    const int Ss[4] = {0, 4096, 5120, 5376};
    float a = 0.f;

#pragma unroll
    for (int l = 0; l < NLVL; l++) {
        const int   HH = Ls[l];
        const float fH = (float)HH;
        const float* vb = val + (((long)b * LQ + Ss[l]) * NH + h) * DH + lane;
#pragma unroll
        for (int p = 0; p < NPT; p++) {
            const int si = l * NPT + p;
            const float ox = ob[si * 2];
            const float oy = ob[si * 2 + 1];
            const float aw = __shfl_sync(0xffffffffu, wgt, si);
            const float xx = refx * fH + ox - 0.5f;
            const float yy = refy * fH + oy - 0.5f;
            const float xf = floorf(xx), yf = floorf(yy);
            const int   x0 = (int)xf, y0 = (int)yf;
            const float dx = xx - xf, dy = yy - yf;
            float sv = 0.f;
#pragma unroll
            for (int t = 0; t < 4; t++) {
                const int   xi = x0 + (t & 1);
                const int   yi = y0 + (t >> 1);
                const float wt = ((t & 1) ? dx : 1.f - dx) * ((t >> 1) ? dy : 1.f - dy);
                if (xi >= 0 && xi < HH && yi >= 0 && yi < HH && wt != 0.f)
                    sv += wt * vb[(long)(yi * HH + xi) * (NH * DH)];
            }
            a += aw * sv;
        }
    }
    acc[rowhead * DH + lane] = a;
}

__global__ void __launch_bounds__(256) add_ln_kernel(
    const float* __restrict__ x, const float* __restrict__ r,
    const float* __restrict__ g, const float* __restrict__ bta,
    float* __restrict__ out)
{
    const int row  = blockIdx.x * 8 + (threadIdx.x >> 5);
    const int lane = threadIdx.x & 31;
    const float* xr = x + (long)row * DMODEL;
    const float* rr = r + (long)row * DMODEL;

    float v[8];
    float sum = 0.f;
#pragma unroll
    for (int k = 0; k < 8; k++) {
        v[k] = xr[lane + 32 * k] + rr[lane + 32 * k];
        sum += v[k];
    }
    sum = warp_sum(sum);
    const float mu = sum * (1.f / 256.f);
    float vs = 0.f;
#pragma unroll
    for (int k = 0; k < 8; k++) { float d = v[k] - mu; vs += d * d; }
    vs = warp_sum(vs) * (1.f / 256.f);
    const float inv = rsqrtf(vs + 1e-5f);
#pragma unroll
    for (int k = 0; k < 8; k++) {
        const int c = lane + 32 * k;
        out[(long)row * DMODEL + c] = (v[k] - mu) * inv * g[c] + bta[c];
    }
}

// ---------------- host orchestration ----------------
static void tcgemm(const float* A, const __nv_bfloat16* Bh, const __nv_bfloat16* Bl,
                   const float* bias, float* C, int K, int N, int relu)
{
    dim3 grid(N / 128, MROWS / 128);
    mma_gemm<<<grid, 256>>>(A, Bh, Bl, bias, C, K, N, relu);
}

extern "C" void kernel_launch(void* const* d_in, const int* in_sizes, int n_in,
                              void* d_out, int out_size)
{
    // inputs may arrive interleaved (src0,pos0,src1,pos1,...) per dict order
    const float* src[4];
    const float* pos[4];
    if (in_sizes[1] == in_sizes[0]) {
        for (int i = 0; i < 4; i++) {
            src[i] = (const float*)d_in[2 * i];
            pos[i] = (const float*)d_in[2 * i + 1];
        }
    } else {
        for (int i = 0; i < 4; i++) {
            src[i] = (const float*)d_in[i];
            pos[i] = (const float*)d_in[4 + i];
        }
    }
    const float* lenc  = (const float*)d_in[8];
    const float* Wv    = (const float*)d_in[9];
    const float* bv    = (const float*)d_in[10];
    const float* Wo    = (const float*)d_in[11];
    const float* bo    = (const float*)d_in[12];
    const float* Wa    = (const float*)d_in[13];
    const float* ba    = (const float*)d_in[14];
    const float* Wout  = (const float*)d_in[15];
    const float* bout  = (const float*)d_in[16];
    const float* ln1g  = (const float*)d_in[17];
    const float* ln1b  = (const float*)d_in[18];
    const float* W1    = (const float*)d_in[19];
    const float* b1    = (const float*)d_in[20];
    const float* W2    = (const float*)d_in[21];
    const float* b2    = (const float*)d_in[22];
    const float* ln2g  = (const float*)d_in[23];
    const float* ln2b  = (const float*)d_in[24];
    float* out = (float*)d_out;

    float *x, *posb, *qb, *vb, *ob, *ab, *accb, *tmpb, *hb;
    cudaGetSymbolAddress((void**)&x,    g_x);
    cudaGetSymbolAddress((void**)&posb, g_pos);
    cudaGetSymbolAddress((void**)&qb,   g_q);
    cudaGetSymbolAddress((void**)&vb,   g_val);
    cudaGetSymbolAddress((void**)&ob,   g_off);
    cudaGetSymbolAddress((void**)&ab,   g_attn);
    cudaGetSymbolAddress((void**)&accb, g_acc);
    cudaGetSymbolAddress((void**)&tmpb, g_tmp);
    cudaGetSymbolAddress((void**)&hb,   g_h);

    __nv_bfloat16 *wvh, *wvl, *woh, *wol, *wah, *wal, *wuh, *wul, *w1h, *w1l, *w2h, *w2l;
    cudaGetSymbolAddress((void**)&wvh, g_wv_h); cudaGetSymbolAddress((void**)&wvl, g_wv_l);
    cudaGetSymbolAddress((void**)&woh, g_wo_h); cudaGetSymbolAddress((void**)&wol, g_wo_l);
    cudaGetSymbolAddress((void**)&wah, g_wa_h); cudaGetSymbolAddress((void**)&wal, g_wa_l);
    cudaGetSymbolAddress((void**)&wuh, g_wu_h); cudaGetSymbolAddress((void**)&wul, g_wu_l);
    cudaGetSymbolAddress((void**)&w1h, g_w1_h); cudaGetSymbolAddress((void**)&w1l, g_w1_l);
    cudaGetSymbolAddress((void**)&w2h, g_w2_h); cudaGetSymbolAddress((void**)&w2l, g_w2_l);

    // transpose + split all weights (W[K,N] -> Wt[N,K] hi/lo)
    {
        dim3 blk(32, 32);
        wsplit_kernel<<<dim3(256 / 32, 256 / 32, NLAYERS), blk>>>(Wv,   wvh, wvl, 256, 256);
        wsplit_kernel<<<dim3(256 / 32, 256 / 32, NLAYERS), blk>>>(Wo,   woh, wol, 256, 256);
        wsplit_kernel<<<dim3(128 / 32, 256 / 32, NLAYERS), blk>>>(Wa,   wah, wal, 256, 128);
        wsplit_kernel<<<dim3(256 / 32, 256 / 32, NLAYERS), blk>>>(Wout, wuh, wul, 256, 256);
        wsplit_kernel<<<dim3(1024 / 32, 256 / 32, NLAYERS), blk>>>(W1,  w1h, w1l, 256, 1024);
        wsplit_kernel<<<dim3(256 / 32, 1024 / 32, NLAYERS), blk>>>(W2,  w2h, w2l, 1024, 256);
    }

    const int M = MROWS;
    // flatten inputs
    {
        dim3 grid(LQ / 32, DMODEL / 32, BATCH);
        dim3 blk(32, 32);
        flatten_kernel<<<grid, blk>>>(src[0], src[1], src[2], src[3],
                                      pos[0], pos[1], pos[2], pos[3],
                                      lenc, x, posb);
    }

    const int n4 = M * DMODEL / 4;
    const int add_blocks = (n4 + 255) / 256;
    const int sample_blocks = (M * NH * 32) / 256;
    const int ln_blocks = M / 8;

    for (int i = 0; i < NLAYERS; i++) {
        const size_t o64k = (size_t)i * 256 * 256;
        const size_t o32k = (size_t)i * 128 * 256;
        const size_t o256k = (size_t)i * 1024 * 256;

        // value = x @ Wv + bv
        tcgemm(x, wvh + o64k, wvl + o64k, bv + (size_t)i * 256, vb, 256, 256, 0);
        // q = x + pos
        add_kernel<<<add_blocks, 256>>>(x, posb, qb, n4);
        // offsets, attn logits
        tcgemm(qb, woh + o64k, wol + o64k, bo + (size_t)i * 256, ob, 256, 256, 0);
        tcgemm(qb, wah + o32k, wal + o32k, ba + (size_t)i * 128, ab, 256, 128, 0);
        // softmax + deformable sampling
        sample_kernel<<<sample_blocks, 256>>>(vb, ob, ab, accb);
        // output projection
        tcgemm(accb, wuh + o64k, wul + o64k, bout + (size_t)i * 256, tmpb, 256, 256, 0);
        // x = LN(x + attn_out)
        add_ln_kernel<<<ln_blocks, 256>>>(x, tmpb, ln1g + (size_t)i * 256,
                                          ln1b + (size_t)i * 256, x);
        // FFN
        tcgemm(x, w1h + o256k, w1l + o256k, b1 + (size_t)i * 1024, hb, 256, 1024, 1);
        tcgemm(hb, w2h + o256k, w2l + o256k, b2 + (size_t)i * 256, tmpb, 1024, 256, 0);
        // x = LN(x + ffn_out)
        float* dst = (i == NLAYERS - 1) ? out : x;
        add_ln_kernel<<<ln_blocks, 256>>>(x, tmpb, ln2g + (size_t)i * 256,
                                          ln2b + (size_t)i * 256, dst);
    }
}

// round 6
// speedup vs baseline: 1.9135x; 1.1267x over previous
#include <cuda_runtime.h>
#include <cuda_bf16.h>
#include <cstdint>

// ---------------- problem constants ----------------
#define BATCH   8
#define DMODEL  256
#define NH      8
#define NLVL    4
#define NPT     4
#define DH      32
#define NLAYERS 6
#define DFF     1024
#define LQ      5440            // 4096 + 1024 + 256 + 64
#define MROWS   (BATCH * LQ)    // 43520

typedef __nv_bfloat16 bf16;

// ---------------- scratch (device globals; no allocation allowed) ----------------
__device__ __align__(16) float g_x   [MROWS * DMODEL];
__device__ __align__(16) float g_pos [MROWS * DMODEL];
__device__ __align__(16) float g_val [MROWS * DMODEL];
__device__ __align__(16) float g_off [MROWS * 384];     // combined offsets(256)+logits(128)
__device__ __align__(16) float g_tmp [MROWS * DMODEL];

__device__ __align__(16) bf16 g_xh [MROWS * DMODEL];
__device__ __align__(16) bf16 g_xl [MROWS * DMODEL];
__device__ __align__(16) bf16 g_qh [MROWS * DMODEL];
__device__ __align__(16) bf16 g_ql [MROWS * DMODEL];
__device__ __align__(16) bf16 g_ach[MROWS * DMODEL];
__device__ __align__(16) bf16 g_acl[MROWS * DMODEL];
__device__ __align__(16) bf16 g_hh [MROWS * DFF];
__device__ __align__(16) bf16 g_hl [MROWS * DFF];

// split-bf16 weights, transposed to [N, K] K-major, hi + lo
__device__ __align__(16) bf16 g_wv_h [NLAYERS * 256 * 256];
__device__ __align__(16) bf16 g_wv_l [NLAYERS * 256 * 256];
__device__ __align__(16) bf16 g_woa_h[NLAYERS * 384 * 256];   // Wo rows 0-255, Wa rows 256-383
__device__ __align__(16) bf16 g_woa_l[NLAYERS * 384 * 256];
__device__ __align__(16) bf16 g_wu_h [NLAYERS * 256 * 256];
__device__ __align__(16) bf16 g_wu_l [NLAYERS * 256 * 256];
__device__ __align__(16) bf16 g_w1_h [NLAYERS * 1024 * 256];
__device__ __align__(16) bf16 g_w1_l [NLAYERS * 1024 * 256];
__device__ __align__(16) bf16 g_w2_h [NLAYERS * 256 * 1024];
__device__ __align__(16) bf16 g_w2_l [NLAYERS * 256 * 1024];
__device__ __align__(16) float g_boa [NLAYERS * 384];

// ---------------- helpers ----------------
__device__ __forceinline__ uint32_t smem_u32(const void* p) {
    uint32_t a;
    asm("{ .reg .u64 t; cvta.to.shared.u64 t, %1; cvt.u32.u64 %0, t; }"
        : "=r"(a) : "l"(p));
    return a;
}
__device__ __forceinline__ void ldm4(uint32_t* r, uint32_t addr) {
    asm volatile("ldmatrix.sync.aligned.m8n8.x4.shared.b16 {%0,%1,%2,%3}, [%4];"
                 : "=r"(r[0]), "=r"(r[1]), "=r"(r[2]), "=r"(r[3]) : "r"(addr));
}
__device__ __forceinline__ void mma16816(float* c, const uint32_t* a,
                                         const uint32_t* b) {
    asm volatile(
        "mma.sync.aligned.m16n8k16.row.col.f32.bf16.bf16.f32 "
        "{%0,%1,%2,%3}, {%4,%5,%6,%7}, {%8,%9}, {%0,%1,%2,%3};"
        : "+f"(c[0]), "+f"(c[1]), "+f"(c[2]), "+f"(c[3])
        : "r"(a[0]), "r"(a[1]), "r"(a[2]), "r"(a[3]), "r"(b[0]), "r"(b[1]));
}
__device__ __forceinline__ uint32_t b2u(__nv_bfloat162 v) {
    return *reinterpret_cast<uint32_t*>(&v);
}
#define CP_ASYNC16(d, s) \
    asm volatile("cp.async.cg.shared.global [%0], [%1], 16;" :: "r"(d), "l"(s))
#define CP_COMMIT() asm volatile("cp.async.commit_group;" ::: "memory")
#define CP_WAIT(n)  asm volatile("cp.async.wait_group %0;" :: "n"(n) : "memory")

// ---------------- weight transpose + bf16 split ----------------
// W[K,N] (per layer) -> Wt_hi/lo[Ntot,K] rows [rowoff, rowoff+N)
__global__ void wsplit_kernel(const float* __restrict__ W,
                              bf16* __restrict__ hi, bf16* __restrict__ lo,
                              int K, int N, int Ntot, int rowoff)
{
    __shared__ float t[32][33];
    const int l = blockIdx.z;
    const float* Wl = W + (size_t)l * K * N;
    const int k0 = blockIdx.y * 32, n0 = blockIdx.x * 32;
    t[threadIdx.y][threadIdx.x] = Wl[(size_t)(k0 + threadIdx.y) * N + n0 + threadIdx.x];
    __syncthreads();
    const float v = t[threadIdx.x][threadIdx.y];
    const bf16 h = __float2bfloat16(v);
    const size_t o = ((size_t)l * Ntot + rowoff + n0 + threadIdx.y) * K + k0 + threadIdx.x;
    hi[o] = h;
    lo[o] = __float2bfloat16(v - __bfloat162float(h));
}

__global__ void bpack_kernel(const float* __restrict__ bo, const float* __restrict__ ba,
                             float* __restrict__ boa)
{
    const int l = blockIdx.x, t = threadIdx.x;   // 384 threads
    boa[l * 384 + t] = (t < 256) ? bo[l * 256 + t] : ba[l * 128 + (t - 256)];
}

// ---------------- pipelined split-bf16 mma.sync GEMM ----------------
// C[M,N] = (Ah+Al)[M,K] @ (Bh+Bl)[N,K]^T + bias  (3 passes: AhBh+AhBl+AlBh)
// CTA 128x128, 8 warps 2x4, warp tile 64x32, BK=32, cp.async 2-stage.
// mode 0: write fp32 Cf.  mode 1: relu, write split bf16 Ch/Cl.
#define GPITCH 80
#define STG    40960   // bytes per stage: 4 tiles x 10240

__global__ void __launch_bounds__(256, 2) mma_gemm(
    const bf16* __restrict__ Ah, const bf16* __restrict__ Al,
    const bf16* __restrict__ Bh, const bf16* __restrict__ Bl,
    const float* __restrict__ bias, float* __restrict__ Cf,
    bf16* __restrict__ Ch, bf16* __restrict__ Cl,
    int K, int N, int mode)
{
    extern __shared__ __align__(16) uint8_t sm[];
    const uint32_t sb = smem_u32(sm);

    const int tid = threadIdx.x;
    const int wid = tid >> 5, lane = tid & 31;
    const int wm = wid >> 2, wn = wid & 3;
    const int m0 = blockIdx.y * 128, n0 = blockIdx.x * 128;
    const int m0w = wm * 64, n0w = wn * 32;
    const int tlq = lane >> 3, rlq = lane & 7;

    const bf16* gb[4] = {Ah + (size_t)m0 * K, Al + (size_t)m0 * K,
                         Bh + (size_t)n0 * K, Bl + (size_t)n0 * K};

    float acc[4][4][4];
#pragma unroll
    for (int i = 0; i < 4; i++)
#pragma unroll
        for (int j = 0; j < 4; j++)
#pragma unroll
            for (int c = 0; c < 4; c++) acc[i][j][c] = 0.f;

    const int nchunk = K >> 5;

    // stage copier: 8 x 16B cp.async per thread (A_h, A_l, B_h, B_l tiles)
    auto docopy = [&](int ch) {
        const int k0 = ch << 5;
        const uint32_t sbase = sb + (uint32_t)(ch & 1) * STG;
#pragma unroll
        for (int j = 0; j < 8; j++) {
            const int buf = j >> 1;                    // compile-time per unrolled j
            const int s = tid + ((j & 1) << 8);        // 0..511 within tile
            const int row = s >> 2, seg = s & 3;
            const bf16* g = gb[buf] + (size_t)row * K + k0 + seg * 8;
            const uint32_t d = sbase + buf * 10240 + row * GPITCH + seg * 16;
            CP_ASYNC16(d, g);
        }
        CP_COMMIT();
    };

    docopy(0);
    for (int ch = 0; ch < nchunk; ch++) {
        if (ch + 1 < nchunk) { docopy(ch + 1); CP_WAIT(1); }
        else                 { CP_WAIT(0); }
        __syncthreads();

        const uint32_t soff = sb + (uint32_t)(ch & 1) * STG;
#pragma unroll
        for (int ks = 0; ks < 2; ks++) {
            const int kk = ks * 16;
            uint32_t af[16], bfr[16];

            // A hi fragments
#pragma unroll
            for (int mi = 0; mi < 4; mi++) {
                const int r = m0w + mi * 16 + rlq + ((tlq & 1) << 3);
                const int kc = kk + ((tlq >> 1) << 3);
                ldm4(af + mi * 4, soff + r * GPITCH + kc * 2);
            }
            // B hi fragments
#pragma unroll
            for (int nj = 0; nj < 2; nj++) {
                const int r = n0w + nj * 16 + rlq + ((tlq >> 1) << 3);
                const int kc = kk + ((tlq & 1) << 3);
                ldm4(bfr + nj * 4, soff + 20480 + r * GPITCH + kc * 2);
            }
            // pass 1: Ah*Bh
#pragma unroll
            for (int mi = 0; mi < 4; mi++)
#pragma unroll
                for (int ni = 0; ni < 4; ni++) {
                    uint32_t b2r[2] = {bfr[(ni >> 1) * 4 + (ni & 1) * 2],
                                       bfr[(ni >> 1) * 4 + (ni & 1) * 2 + 1]};
                    mma16816(acc[mi][ni], af + mi * 4, b2r);
                }
            // B lo fragments
#pragma unroll
            for (int nj = 0; nj < 2; nj++) {
                const int r = n0w + nj * 16 + rlq + ((tlq >> 1) << 3);
                const int kc = kk + ((tlq & 1) << 3);
                ldm4(bfr + 8 + nj * 4, soff + 30720 + r * GPITCH + kc * 2);
            }
            // pass 2: Ah*Bl
#pragma unroll
            for (int mi = 0; mi < 4; mi++)
#pragma unroll
                for (int ni = 0; ni < 4; ni++) {
                    uint32_t b2r[2] = {bfr[8 + (ni >> 1) * 4 + (ni & 1) * 2],
                                       bfr[8 + (ni >> 1) * 4 + (ni & 1) * 2 + 1]};
                    mma16816(acc[mi][ni], af + mi * 4, b2r);
                }
            // A lo fragments
#pragma unroll
            for (int mi = 0; mi < 4; mi++) {
                const int r = m0w + mi * 16 + rlq + ((tlq & 1) << 3);
                const int kc = kk + ((tlq >> 1) << 3);
                ldm4(af + mi * 4, soff + 10240 + r * GPITCH + kc * 2);
            }
            // pass 3: Al*Bh
#pragma unroll
            for (int mi = 0; mi < 4; mi++)
#pragma unroll
                for (int ni = 0; ni < 4; ni++) {
                    uint32_t b2r[2] = {bfr[(ni >> 1) * 4 + (ni & 1) * 2],
                                       bfr[(ni >> 1) * 4 + (ni & 1) * 2 + 1]};
                    mma16816(acc[mi][ni], af + mi * 4, b2r);
                }
        }
        __syncthreads();
    }

    // ---- epilogue ----
    const int g = lane >> 2, tg = lane & 3;
#pragma unroll
    for (int mi = 0; mi < 4; mi++) {
        const int r0 = m0 + m0w + mi * 16 + g;
#pragma unroll
        for (int ni = 0; ni < 4; ni++) {
            const int col = n0 + n0w + ni * 8 + tg * 2;
            const float b0 = bias[col], b1 = bias[col + 1];
            float v00 = acc[mi][ni][0] + b0, v01 = acc[mi][ni][1] + b1;
            float v10 = acc[mi][ni][2] + b0, v11 = acc[mi][ni][3] + b1;
            if (mode == 0) {
                *(float2*)(Cf + (size_t)r0 * N + col)       = make_float2(v00, v01);
                *(float2*)(Cf + (size_t)(r0 + 8) * N + col) = make_float2(v10, v11);
            } else {
                v00 = fmaxf(v00, 0.f); v01 = fmaxf(v01, 0.f);
                v10 = fmaxf(v10, 0.f); v11 = fmaxf(v11, 0.f);
                bf16 h00 = __float2bfloat16(v00), h01 = __float2bfloat16(v01);
                bf16 h10 = __float2bfloat16(v10), h11 = __float2bfloat16(v11);
                bf16 l00 = __float2bfloat16(v00 - __bfloat162float(h00));
                bf16 l01 = __float2bfloat16(v01 - __bfloat162float(h01));
                bf16 l10 = __float2bfloat16(v10 - __bfloat162float(h10));
                bf16 l11 = __float2bfloat16(v11 - __bfloat162float(h11));
                *(uint32_t*)(Ch + (size_t)r0 * N + col)       = b2u(__halves2bfloat162(h00, h01));
                *(uint32_t*)(Cl + (size_t)r0 * N + col)       = b2u(__halves2bfloat162(l00, l01));
                *(uint32_t*)(Ch + (size_t)(r0 + 8) * N + col) = b2u(__halves2bfloat162(h10, h11));
                *(uint32_t*)(Cl + (size_t)(r0 + 8) * N + col) = b2u(__halves2bfloat162(l10, l11));
            }
        }
    }
}

// ---------------- non-GEMM kernels ----------------
__device__ __forceinline__ float warp_sum(float v) {
#pragma unroll
    for (int o = 16; o > 0; o >>= 1) v += __shfl_xor_sync(0xffffffffu, v, o);
    return v;
}
__device__ __forceinline__ float half_sum16(float v) {
#pragma unroll
    for (int o = 8; o > 0; o >>= 1) v += __shfl_xor_sync(0xffffffffu, v, o);
    return v;
}
__device__ __forceinline__ float half_max16(float v) {
#pragma unroll
    for (int o = 8; o > 0; o >>= 1) v = fmaxf(v, __shfl_xor_sync(0xffffffffu, v, o));
    return v;
}
__device__ __forceinline__ void split_store(bf16* h, bf16* l, size_t idx, float v) {
    bf16 hv = __float2bfloat16(v);
    h[idx] = hv;
    l[idx] = __float2bfloat16(v - __bfloat162float(hv));
}

// flatten: (B,D,H,W) -> x fp32 + split, pos fp32, q=x+pos split
__global__ void flatten_kernel(const float* __restrict__ s0, const float* __restrict__ s1,
                               const float* __restrict__ s2, const float* __restrict__ s3,
                               const float* __restrict__ p0, const float* __restrict__ p1,
                               const float* __restrict__ p2, const float* __restrict__ p3,
                               const float* __restrict__ lenc,
                               float* __restrict__ x, float* __restrict__ pos,
                               bf16* __restrict__ xh, bf16* __restrict__ xl,
                               bf16* __restrict__ qh, bf16* __restrict__ ql)
{
    __shared__ float ts[32][33];
    __shared__ float tp[32][33];
    const int b  = blockIdx.z;
    const int q0 = blockIdx.x * 32;
    const int d0 = blockIdx.y * 32;

    int l, start, HW;
    const float *src, *pp;
    if (q0 < 4096)      { l = 0; start = 0;    HW = 4096; src = s0; pp = p0; }
    else if (q0 < 5120) { l = 1; start = 4096; HW = 1024; src = s1; pp = p1; }
    else if (q0 < 5376) { l = 2; start = 5120; HW = 256;  src = s2; pp = p2; }
    else                { l = 3; start = 5376; HW = 64;   src = s3; pp = p3; }

    const int pix0 = q0 - start;
    const int tx = threadIdx.x, ty = threadIdx.y;

    long sidx = ((long)b * DMODEL + (d0 + ty)) * HW + pix0 + tx;
    ts[ty][tx] = src[sidx];
    tp[ty][tx] = pp[sidx];
    __syncthreads();

    const int q  = q0 + ty;
    const int dd = d0 + tx;
    const size_t oidx = ((size_t)b * LQ + q) * DMODEL + dd;
    const float xv = ts[tx][ty];
    const float pv = tp[tx][ty] + lenc[l * DMODEL + dd];
    x[oidx]   = xv;
    pos[oidx] = pv;
    split_store(xh, xl, oidx, xv);
    split_store(qh, ql, oidx, xv + pv);
}

// deformable sampling + fused softmax; one warp per (b,q,h)
// combined proj layout: row stride 384; offsets at h*32, logits at 256 + h*16
__global__ void __launch_bounds__(256) sample_kernel(
    const float* __restrict__ val, const float* __restrict__ proj,
    bf16* __restrict__ acch, bf16* __restrict__ accl)
{
    const int gwid = (blockIdx.x * blockDim.x + threadIdx.x) >> 5;
    const int lane = threadIdx.x & 31;
    const int h = gwid % NH;
    const int q = (gwid / NH) % LQ;
    const int b = gwid / (NH * LQ);

    const size_t rowq = (size_t)b * LQ + q;
    const float* pr = proj + rowq * 384;

    float lv = pr[256 + h * 16 + (lane & 15)];
    float mx = half_max16(lv);
    float e  = __expf(lv - mx);
    float s  = half_sum16(e);
    float wgt = e / s;

    int W0, start0;
    if (q < 4096)      { W0 = 64; start0 = 0;    }
    else if (q < 5120) { W0 = 32; start0 = 4096; }
    else if (q < 5376) { W0 = 16; start0 = 5120; }
    else               { W0 = 8;  start0 = 5376; }
    const int pix = q - start0;
    const float refx = ((pix % W0) + 0.5f) / (float)W0;
    const float refy = ((pix / W0) + 0.5f) / (float)W0;

    const float* ob = pr + h * 32;
    const int Ls[4] = {64, 32, 16, 8};
    const int Ss[4] = {0, 4096, 5120, 5376};
    float a = 0.f;

#pragma unroll
    for (int l = 0; l < NLVL; l++) {
        const int   HH = Ls[l];
        const float fH = (float)HH;
        const float* vb = val + (((size_t)b * LQ + Ss[l]) * NH + h) * DH + lane;
#pragma unroll
        for (int p = 0; p < NPT; p++) {
            const int si = l * NPT + p;
            const float ox = ob[si * 2];
            const float oy = ob[si * 2 + 1];
            const float aw = __shfl_sync(0xffffffffu, wgt, si);
            const float xx = refx * fH + ox - 0.5f;
            const float yy = refy * fH + oy - 0.5f;
            const float xf = floorf(xx), yf = floorf(yy);
            const int   x0 = (int)xf, y0 = (int)yf;
            const float dx = xx - xf, dy = yy - yf;
            float sv = 0.f;
#pragma unroll
            for (int t = 0; t < 4; t++) {
                const int   xi = x0 + (t & 1);
                const int   yi = y0 + (t >> 1);
                const float wt = ((t & 1) ? dx : 1.f - dx) * ((t >> 1) ? dy : 1.f - dy);
                if (xi >= 0 && xi < HH && yi >= 0 && yi < HH && wt != 0.f)
                    sv += wt * vb[(size_t)(yi * HH + xi) * (NH * DH)];
            }
            a += aw * sv;
        }
    }
    const size_t oi = (rowq * NH + h) * DH + lane;
    split_store(acch, accl, oi, a);
}

// fused residual-add + LayerNorm; optional split out; optional q=out+pos split
// flags bit0: write oh/ol split; bit1: write qh/ql = split(out + pos)
__global__ void __launch_bounds__(256) add_ln_kernel(
    const float* __restrict__ x, const float* __restrict__ r,
    const float* __restrict__ g, const float* __restrict__ bta,
    float* __restrict__ out,
    bf16* __restrict__ oh, bf16* __restrict__ ol,
    const float* __restrict__ pos,
    bf16* __restrict__ qh, bf16* __restrict__ ql,
    int flags)
{
    const int row  = blockIdx.x * 8 + (threadIdx.x >> 5);
    const int lane = threadIdx.x & 31;
    const size_t base = (size_t)row * DMODEL;
    const float* xr = x + base;
    const float* rr = r + base;

    float v[8];
    float sum = 0.f;
#pragma unroll
    for (int k = 0; k < 8; k++) {
        v[k] = xr[lane + 32 * k] + rr[lane + 32 * k];
        sum += v[k];
    }
    sum = warp_sum(sum);
    const float mu = sum * (1.f / 256.f);
    float vs = 0.f;
#pragma unroll
    for (int k = 0; k < 8; k++) { float d = v[k] - mu; vs += d * d; }
    vs = warp_sum(vs) * (1.f / 256.f);
    const float inv = rsqrtf(vs + 1e-5f);
#pragma unroll
    for (int k = 0; k < 8; k++) {
        const int c = lane + 32 * k;
        const float o = (v[k] - mu) * inv * g[c] + bta[c];
        out[base + c] = o;
        if (flags & 1) split_store(oh, ol, base + c, o);
        if (flags & 2) split_store(qh, ql, base + c, o + pos[base + c]);
    }
}

// ---------------- host orchestration ----------------
static void tcgemm(const bf16* Ah, const bf16* Al, const bf16* Bh, const bf16* Bl,
                   const float* bias, float* Cf, bf16* Ch, bf16* Cl,
                   int K, int N, int mode)
{
    dim3 grid(N / 128, MROWS / 128);
    mma_gemm<<<grid, 256, 2 * STG>>>(Ah, Al, Bh, Bl, bias, Cf, Ch, Cl, K, N, mode);
}

extern "C" void kernel_launch(void* const* d_in, const int* in_sizes, int n_in,
                              void* d_out, int out_size)
{
    cudaFuncSetAttribute(mma_gemm, cudaFuncAttributeMaxDynamicSharedMemorySize, 2 * STG);

    // inputs may arrive interleaved (src0,pos0,src1,pos1,...) per dict order
    const float* src[4];
    const float* pos[4];
    if (in_sizes[1] == in_sizes[0]) {
        for (int i = 0; i < 4; i++) {
            src[i] = (const float*)d_in[2 * i];
            pos[i] = (const float*)d_in[2 * i + 1];
        }
    } else {
        for (int i = 0; i < 4; i++) {
            src[i] = (const float*)d_in[i];
            pos[i] = (const float*)d_in[4 + i];
        }
    }
    const float* lenc  = (const float*)d_in[8];
    const float* Wv    = (const float*)d_in[9];
    const float* bv    = (const float*)d_in[10];
    const float* Wo    = (const float*)d_in[11];
    const float* bo    = (const float*)d_in[12];
    const float* Wa    = (const float*)d_in[13];
    const float* ba    = (const float*)d_in[14];
    const float* Wout  = (const float*)d_in[15];
    const float* bout  = (const float*)d_in[16];
    const float* ln1g  = (const float*)d_in[17];
    const float* ln1b  = (const float*)d_in[18];
    const float* W1    = (const float*)d_in[19];
    const float* b1    = (const float*)d_in[20];
    const float* W2    = (const float*)d_in[21];
    const float* b2    = (const float*)d_in[22];
    const float* ln2g  = (const float*)d_in[23];
    const float* ln2b  = (const float*)d_in[24];
    float* out = (float*)d_out;

    float *x, *posb, *vb, *ob, *tmpb, *boa;
    cudaGetSymbolAddress((void**)&x,    g_x);
    cudaGetSymbolAddress((void**)&posb, g_pos);
    cudaGetSymbolAddress((void**)&vb,   g_val);
    cudaGetSymbolAddress((void**)&ob,   g_off);
    cudaGetSymbolAddress((void**)&tmpb, g_tmp);
    cudaGetSymbolAddress((void**)&boa,  g_boa);

    bf16 *xh, *xl, *qh, *ql, *ach, *acl, *hh, *hl;
    cudaGetSymbolAddress((void**)&xh,  g_xh);  cudaGetSymbolAddress((void**)&xl,  g_xl);
    cudaGetSymbolAddress((void**)&qh,  g_qh);  cudaGetSymbolAddress((void**)&ql,  g_ql);
    cudaGetSymbolAddress((void**)&ach, g_ach); cudaGetSymbolAddress((void**)&acl, g_acl);
    cudaGetSymbolAddress((void**)&hh,  g_hh);  cudaGetSymbolAddress((void**)&hl,  g_hl);

    bf16 *wvh, *wvl, *woah, *woal, *wuh, *wul, *w1h, *w1l, *w2h, *w2l;
    cudaGetSymbolAddress((void**)&wvh,  g_wv_h);  cudaGetSymbolAddress((void**)&wvl,  g_wv_l);
    cudaGetSymbolAddress((void**)&woah, g_woa_h); cudaGetSymbolAddress((void**)&woal, g_woa_l);
    cudaGetSymbolAddress((void**)&wuh,  g_wu_h);  cudaGetSymbolAddress((void**)&wul,  g_wu_l);
    cudaGetSymbolAddress((void**)&w1h,  g_w1_h);  cudaGetSymbolAddress((void**)&w1l,  g_w1_l);
    cudaGetSymbolAddress((void**)&w2h,  g_w2_h);  cudaGetSymbolAddress((void**)&w2l,  g_w2_l);

    // weight prep
    {
        dim3 blk(32, 32);
        wsplit_kernel<<<dim3(8, 8, NLAYERS), blk>>>(Wv,   wvh, wvl, 256, 256, 256, 0);
        wsplit_kernel<<<dim3(8, 8, NLAYERS), blk>>>(Wo,   woah, woal, 256, 256, 384, 0);
        wsplit_kernel<<<dim3(4, 8, NLAYERS), blk>>>(Wa,   woah, woal, 256, 128, 384, 256);
        wsplit_kernel<<<dim3(8, 8, NLAYERS), blk>>>(Wout, wuh, wul, 256, 256, 256, 0);
        wsplit_kernel<<<dim3(32, 8, NLAYERS), blk>>>(W1,  w1h, w1l, 256, 1024, 1024, 0);
        wsplit_kernel<<<dim3(8, 32, NLAYERS), blk>>>(W2,  w2h, w2l, 1024, 256, 256, 0);
        bpack_kernel<<<NLAYERS, 384>>>(bo, ba, boa);
    }

    // flatten inputs (+ x split, q split for layer 0)
    {
        dim3 grid(LQ / 32, DMODEL / 32, BATCH);
        dim3 blk(32, 32);
        flatten_kernel<<<grid, blk>>>(src[0], src[1], src[2], src[3],
                                      pos[0], pos[1], pos[2], pos[3],
                                      lenc, x, posb, xh, xl, qh, ql);
    }

    const int sample_blocks = (MROWS * NH * 32) / 256;
    const int ln_blocks = MROWS / 8;

    for (int i = 0; i < NLAYERS; i++) {
        const size_t o64k  = (size_t)i * 256 * 256;
        const size_t o96k  = (size_t)i * 384 * 256;
        const size_t o256k = (size_t)i * 1024 * 256;

        // value = x @ Wv + bv   (fp32 out for sampling)
        tcgemm(xh, xl, wvh + o64k, wvl + o64k, bv + (size_t)i * 256,
               vb, nullptr, nullptr, 256, 256, 0);
        // combined offsets+logits = q @ [Wo|Wa] + [bo|ba]
        tcgemm(qh, ql, woah + o96k, woal + o96k, boa + (size_t)i * 384,
               ob, nullptr, nullptr, 256, 384, 0);
        // softmax + deformable sampling -> split bf16 acc
        sample_kernel<<<sample_blocks, 256>>>(vb, ob, ach, acl);
        // output projection
        tcgemm(ach, acl, wuh + o64k, wul + o64k, bout + (size_t)i * 256,
               tmpb, nullptr, nullptr, 256, 256, 0);
        // x = LN(x + attn); split for W1
        add_ln_kernel<<<ln_blocks, 256>>>(x, tmpb, ln1g + (size_t)i * 256,
                                          ln1b + (size_t)i * 256, x,
                                          xh, xl, nullptr, nullptr, nullptr, 1);
        // FFN: h = relu(x @ W1 + b1) -> split bf16
        tcgemm(xh, xl, w1h + o256k, w1l + o256k, b1 + (size_t)i * 1024,
               nullptr, hh, hl, 256, 1024, 1);
        tcgemm(hh, hl, w2h + o256k, w2l + o256k, b2 + (size_t)i * 256,
               tmpb, nullptr, nullptr, 1024, 256, 0);
        // x = LN(x + ffn); split x for next Wv; q = x + pos split for next layer
        const int last = (i == NLAYERS - 1);
        add_ln_kernel<<<ln_blocks, 256>>>(x, tmpb, ln2g + (size_t)i * 256,
                                          ln2b + (size_t)i * 256,
                                          last ? out : x,
                                          xh, xl, posb, qh, ql, last ? 0 : 3);
    }
}

// round 7
// speedup vs baseline: 2.1430x; 1.1199x over previous
#include <cuda_runtime.h>
#include <cuda_bf16.h>
#include <cstdint>

// ---------------- problem constants ----------------
#define BATCH   8
#define DMODEL  256
#define NH      8
#define NLVL    4
#define NPT     4
#define DH      32
#define NLAYERS 6
#define DFF     1024
#define LQ      5440            // 4096 + 1024 + 256 + 64
#define MROWS   (BATCH * LQ)    // 43520

typedef __nv_bfloat16 bf16;

// ---------------- scratch (device globals; no allocation allowed) ----------------
__device__ __align__(16) float g_x   [MROWS * DMODEL];
__device__ __align__(16) float g_pos [MROWS * DMODEL];
__device__ __align__(16) float g_val [MROWS * DMODEL];
__device__ __align__(16) float g_off [MROWS * 384];     // combined offsets(256)+logits(128)
__device__ __align__(16) float g_tmp [MROWS * DMODEL];

__device__ __align__(16) bf16 g_xh [MROWS * DMODEL];
__device__ __align__(16) bf16 g_xl [MROWS * DMODEL];
__device__ __align__(16) bf16 g_qh [MROWS * DMODEL];
__device__ __align__(16) bf16 g_ql [MROWS * DMODEL];
__device__ __align__(16) bf16 g_ach[MROWS * DMODEL];
__device__ __align__(16) bf16 g_acl[MROWS * DMODEL];
__device__ __align__(16) bf16 g_hh [MROWS * DFF];
__device__ __align__(16) bf16 g_hl [MROWS * DFF];

// split-bf16 weights, transposed to [N, K] K-major, hi + lo
__device__ __align__(16) bf16 g_wv_h [NLAYERS * 256 * 256];
__device__ __align__(16) bf16 g_wv_l [NLAYERS * 256 * 256];
__device__ __align__(16) bf16 g_woa_h[NLAYERS * 384 * 256];   // Wo rows 0-255, Wa rows 256-383
__device__ __align__(16) bf16 g_woa_l[NLAYERS * 384 * 256];
__device__ __align__(16) bf16 g_wu_h [NLAYERS * 256 * 256];
__device__ __align__(16) bf16 g_wu_l [NLAYERS * 256 * 256];
__device__ __align__(16) bf16 g_w1_h [NLAYERS * 1024 * 256];
__device__ __align__(16) bf16 g_w1_l [NLAYERS * 1024 * 256];
__device__ __align__(16) bf16 g_w2_h [NLAYERS * 256 * 1024];
__device__ __align__(16) bf16 g_w2_l [NLAYERS * 256 * 1024];
__device__ __align__(16) float g_boa [NLAYERS * 384];

// ---------------- low-level helpers ----------------
__device__ __forceinline__ uint32_t smem_u32(const void* p) {
    uint32_t a;
    asm("{ .reg .u64 t; cvta.to.shared.u64 t, %1; cvt.u32.u64 %0, t; }"
        : "=r"(a) : "l"(p));
    return a;
}
__device__ __forceinline__ void ldm4(uint32_t* r, uint32_t addr) {
    asm volatile("ldmatrix.sync.aligned.m8n8.x4.shared.b16 {%0,%1,%2,%3}, [%4];"
                 : "=r"(r[0]), "=r"(r[1]), "=r"(r[2]), "=r"(r[3]) : "r"(addr));
}
__device__ __forceinline__ void mma16816(float* c, const uint32_t* a,
                                         const uint32_t* b) {
    asm volatile(
        "mma.sync.aligned.m16n8k16.row.col.f32.bf16.bf16.f32 "
        "{%0,%1,%2,%3}, {%4,%5,%6,%7}, {%8,%9}, {%0,%1,%2,%3};"
        : "+f"(c[0]), "+f"(c[1]), "+f"(c[2]), "+f"(c[3])
        : "r"(a[0]), "r"(a[1]), "r"(a[2]), "r"(a[3]), "r"(b[0]), "r"(b[1]));
}
__device__ __forceinline__ uint32_t b2u(__nv_bfloat162 v) {
    return *reinterpret_cast<uint32_t*>(&v);
}
#define CP_ASYNC16(d, s) \
    asm volatile("cp.async.cg.shared.global [%0], [%1], 16;" :: "r"(d), "l"(s))
#define CP_COMMIT() asm volatile("cp.async.commit_group;" ::: "memory")
#define CP_WAIT(n)  asm volatile("cp.async.wait_group %0;" :: "n"(n) : "memory")

// ---------------- merged weight prep: all transposes + splits, ONE launch --------
// per-weight tiles (N/32)x(K/32) per layer; segments concatenated over blockIdx.x
__global__ void prep_kernel(
    const float* __restrict__ Wv, const float* __restrict__ Wo,
    const float* __restrict__ Wa, const float* __restrict__ Wout,
    const float* __restrict__ W1, const float* __restrict__ W2,
    bf16* __restrict__ wvh, bf16* __restrict__ wvl,
    bf16* __restrict__ woah, bf16* __restrict__ woal,
    bf16* __restrict__ wuh, bf16* __restrict__ wul,
    bf16* __restrict__ w1h, bf16* __restrict__ w1l,
    bf16* __restrict__ w2h, bf16* __restrict__ w2l)
{
    __shared__ float t[32][33];
    int bid = blockIdx.x;
    const float* W; bf16 *hi, *lo;
    int K, N, Ntot, rowoff, tpl;
    if (bid < 384)       { W = Wv;   hi = wvh;  lo = wvl;  K = 256;  N = 256;  Ntot = 256;  rowoff = 0;   tpl = 64;  }
    else if (bid < 768)  { bid -= 384;  W = Wo;   hi = woah; lo = woal; K = 256;  N = 256;  Ntot = 384;  rowoff = 0;   tpl = 64;  }
    else if (bid < 960)  { bid -= 768;  W = Wa;   hi = woah; lo = woal; K = 256;  N = 128;  Ntot = 384;  rowoff = 256; tpl = 32;  }
    else if (bid < 1344) { bid -= 960;  W = Wout; hi = wuh;  lo = wul;  K = 256;  N = 256;  Ntot = 256;  rowoff = 0;   tpl = 64;  }
    else if (bid < 2880) { bid -= 1344; W = W1;   hi = w1h;  lo = w1l;  K = 256;  N = 1024; Ntot = 1024; rowoff = 0;   tpl = 256; }
    else                 { bid -= 2880; W = W2;   hi = w2h;  lo = w2l;  K = 1024; N = 256;  Ntot = 256;  rowoff = 0;   tpl = 256; }
    const int l = bid / tpl, tt = bid % tpl;
    const int nt = N / 32;
    const int n0 = (tt % nt) * 32, k0 = (tt / nt) * 32;

    const float* Wl = W + (size_t)l * K * N;
    t[threadIdx.y][threadIdx.x] = Wl[(size_t)(k0 + threadIdx.y) * N + n0 + threadIdx.x];
    __syncthreads();
    const float v = t[threadIdx.x][threadIdx.y];
    const bf16 hv = __float2bfloat16(v);
    const size_t o = ((size_t)l * Ntot + rowoff + n0 + threadIdx.y) * K + k0 + threadIdx.x;
    hi[o] = hv;
    lo[o] = __float2bfloat16(v - __bfloat162float(hv));
}

__global__ void bpack_kernel(const float* __restrict__ bo, const float* __restrict__ ba,
                             float* __restrict__ boa)
{
    const int l = blockIdx.x, t = threadIdx.x;   // 384 threads
    boa[l * 384 + t] = (t < 256) ? bo[l * 256 + t] : ba[l * 128 + (t - 256)];
}

// ---------------- pipelined split-bf16 mma.sync GEMM core ----------------
// C[m0:+128, n0:+128] = (Ah+Al) @ (Bh+Bl)^T + bias  (AhBh + AhBl + AlBh)
// 8 warps 2x4, warp tile 64x32, BK=32, cp.async 2-stage ping-pong.
#define GPITCH 80
#define STG    40960   // bytes per stage: 4 tiles x 10240

__device__ __forceinline__ void gemm_core(
    const bf16* __restrict__ Ah, const bf16* __restrict__ Al,
    const bf16* __restrict__ Bh, const bf16* __restrict__ Bl,
    const float* __restrict__ bias, float* __restrict__ Cf,
    bf16* __restrict__ Ch, bf16* __restrict__ Cl,
    int K, int N, int mode, int m0, int n0, uint8_t* sm)
{
    const uint32_t sb = smem_u32(sm);
    const int tid = threadIdx.x;
    const int wid = tid >> 5, lane = tid & 31;
    const int wm = wid >> 2, wn = wid & 3;
    const int m0w = wm * 64, n0w = wn * 32;
    const int tlq = lane >> 3, rlq = lane & 7;

    const bf16* gb[4] = {Ah + (size_t)m0 * K, Al + (size_t)m0 * K,
                         Bh + (size_t)n0 * K, Bl + (size_t)n0 * K};

    float acc[4][4][4];
#pragma unroll
    for (int i = 0; i < 4; i++)
#pragma unroll
        for (int j = 0; j < 4; j++)
#pragma unroll
            for (int c = 0; c < 4; c++) acc[i][j][c] = 0.f;

    const int nchunk = K >> 5;

    auto docopy = [&](int ch) {
        const int k0 = ch << 5;
        const uint32_t sbase = sb + (uint32_t)(ch & 1) * STG;
#pragma unroll
        for (int j = 0; j < 8; j++) {
            const int buf = j >> 1;
            const int s = tid + ((j & 1) << 8);
            const int row = s >> 2, seg = s & 3;
            const bf16* g = gb[buf] + (size_t)row * K + k0 + seg * 8;
            const uint32_t d = sbase + buf * 10240 + row * GPITCH + seg * 16;
            CP_ASYNC16(d, g);
        }
        CP_COMMIT();
    };

    docopy(0);
    for (int ch = 0; ch < nchunk; ch++) {
        if (ch + 1 < nchunk) { docopy(ch + 1); CP_WAIT(1); }
        else                 { CP_WAIT(0); }
        __syncthreads();

        const uint32_t soff = sb + (uint32_t)(ch & 1) * STG;
#pragma unroll
        for (int ks = 0; ks < 2; ks++) {
            const int kk = ks * 16;
            uint32_t af[16], bfr[16];

#pragma unroll
            for (int mi = 0; mi < 4; mi++) {
                const int r = m0w + mi * 16 + rlq + ((tlq & 1) << 3);
                const int kc = kk + ((tlq >> 1) << 3);
                ldm4(af + mi * 4, soff + r * GPITCH + kc * 2);
            }
#pragma unroll
            for (int nj = 0; nj < 2; nj++) {
                const int r = n0w + nj * 16 + rlq + ((tlq >> 1) << 3);
                const int kc = kk + ((tlq & 1) << 3);
                ldm4(bfr + nj * 4, soff + 20480 + r * GPITCH + kc * 2);
            }
            // pass 1: Ah*Bh
#pragma unroll
            for (int mi = 0; mi < 4; mi++)
#pragma unroll
                for (int ni = 0; ni < 4; ni++) {
                    uint32_t b2r[2] = {bfr[(ni >> 1) * 4 + (ni & 1) * 2],
                                       bfr[(ni >> 1) * 4 + (ni & 1) * 2 + 1]};
                    mma16816(acc[mi][ni], af + mi * 4, b2r);
                }
#pragma unroll
            for (int nj = 0; nj < 2; nj++) {
                const int r = n0w + nj * 16 + rlq + ((tlq >> 1) << 3);
                const int kc = kk + ((tlq & 1) << 3);
                ldm4(bfr + 8 + nj * 4, soff + 30720 + r * GPITCH + kc * 2);
            }
            // pass 2: Ah*Bl
#pragma unroll
            for (int mi = 0; mi < 4; mi++)
#pragma unroll
                for (int ni = 0; ni < 4; ni++) {
                    uint32_t b2r[2] = {bfr[8 + (ni >> 1) * 4 + (ni & 1) * 2],
                                       bfr[8 + (ni >> 1) * 4 + (ni & 1) * 2 + 1]};
                    mma16816(acc[mi][ni], af + mi * 4, b2r);
                }
#pragma unroll
            for (int mi = 0; mi < 4; mi++) {
                const int r = m0w + mi * 16 + rlq + ((tlq & 1) << 3);
                const int kc = kk + ((tlq >> 1) << 3);
                ldm4(af + mi * 4, soff + 10240 + r * GPITCH + kc * 2);
            }
            // pass 3: Al*Bh
#pragma unroll
            for (int mi = 0; mi < 4; mi++)
#pragma unroll
                for (int ni = 0; ni < 4; ni++) {
                    uint32_t b2r[2] = {bfr[(ni >> 1) * 4 + (ni & 1) * 2],
                                       bfr[(ni >> 1) * 4 + (ni & 1) * 2 + 1]};
                    mma16816(acc[mi][ni], af + mi * 4, b2r);
                }
        }
        __syncthreads();
    }

    const int g = lane >> 2, tg = lane & 3;
#pragma unroll
    for (int mi = 0; mi < 4; mi++) {
        const int r0 = m0 + m0w + mi * 16 + g;
#pragma unroll
        for (int ni = 0; ni < 4; ni++) {
            const int col = n0 + n0w + ni * 8 + tg * 2;
            const float b0 = bias[col], b1 = bias[col + 1];
            float v00 = acc[mi][ni][0] + b0, v01 = acc[mi][ni][1] + b1;
            float v10 = acc[mi][ni][2] + b0, v11 = acc[mi][ni][3] + b1;
            if (mode == 0) {
                *(float2*)(Cf + (size_t)r0 * N + col)       = make_float2(v00, v01);
                *(float2*)(Cf + (size_t)(r0 + 8) * N + col) = make_float2(v10, v11);
            } else {
                v00 = fmaxf(v00, 0.f); v01 = fmaxf(v01, 0.f);
                v10 = fmaxf(v10, 0.f); v11 = fmaxf(v11, 0.f);
                bf16 h00 = __float2bfloat16(v00), h01 = __float2bfloat16(v01);
                bf16 h10 = __float2bfloat16(v10), h11 = __float2bfloat16(v11);
                bf16 l00 = __float2bfloat16(v00 - __bfloat162float(h00));
                bf16 l01 = __float2bfloat16(v01 - __bfloat162float(h01));
                bf16 l10 = __float2bfloat16(v10 - __bfloat162float(h10));
                bf16 l11 = __float2bfloat16(v11 - __bfloat162float(h11));
                *(uint32_t*)(Ch + (size_t)r0 * N + col)       = b2u(__halves2bfloat162(h00, h01));
                *(uint32_t*)(Cl + (size_t)r0 * N + col)       = b2u(__halves2bfloat162(l00, l01));
                *(uint32_t*)(Ch + (size_t)(r0 + 8) * N + col) = b2u(__halves2bfloat162(h10, h11));
                *(uint32_t*)(Cl + (size_t)(r0 + 8) * N + col) = b2u(__halves2bfloat162(l10, l11));
            }
        }
    }
}

__global__ void __launch_bounds__(256, 2) mma_gemm(
    const bf16* __restrict__ Ah, const bf16* __restrict__ Al,
    const bf16* __restrict__ Bh, const bf16* __restrict__ Bl,
    const float* __restrict__ bias, float* __restrict__ Cf,
    bf16* __restrict__ Ch, bf16* __restrict__ Cl,
    int K, int N, int mode)
{
    extern __shared__ __align__(16) uint8_t sm[];
    gemm_core(Ah, Al, Bh, Bl, bias, Cf, Ch, Cl, K, N, mode,
              blockIdx.y * 128, blockIdx.x * 128, sm);
}

// fused value + offsets/logits projections (independent, share a launch)
__global__ void __launch_bounds__(256, 2) proj_gemm(
    const bf16* __restrict__ xh, const bf16* __restrict__ xl,
    const bf16* __restrict__ wvh, const bf16* __restrict__ wvl,
    const float* __restrict__ bv, float* __restrict__ vb,
    const bf16* __restrict__ qh, const bf16* __restrict__ ql,
    const bf16* __restrict__ woah, const bf16* __restrict__ woal,
    const float* __restrict__ boa, float* __restrict__ ob)
{
    extern __shared__ __align__(16) uint8_t sm[];
    const int m0 = blockIdx.y * 128, n0 = blockIdx.x * 128;
    if (blockIdx.z == 0) {
        if (blockIdx.x >= 2) return;
        gemm_core(xh, xl, wvh, wvl, bv, vb, nullptr, nullptr, 256, 256, 0, m0, n0, sm);
    } else {
        gemm_core(qh, ql, woah, woal, boa, ob, nullptr, nullptr, 256, 384, 0, m0, n0, sm);
    }
}

// ---------------- non-GEMM kernels ----------------
__device__ __forceinline__ float warp_sum(float v) {
#pragma unroll
    for (int o = 16; o > 0; o >>= 1) v += __shfl_xor_sync(0xffffffffu, v, o);
    return v;
}
__device__ __forceinline__ float half_sum16(float v) {
#pragma unroll
    for (int o = 8; o > 0; o >>= 1) v += __shfl_xor_sync(0xffffffffu, v, o);
    return v;
}
__device__ __forceinline__ float half_max16(float v) {
#pragma unroll
    for (int o = 8; o > 0; o >>= 1) v = fmaxf(v, __shfl_xor_sync(0xffffffffu, v, o));
    return v;
}
__device__ __forceinline__ void split_store(bf16* h, bf16* l, size_t idx, float v) {
    bf16 hv = __float2bfloat16(v);
    h[idx] = hv;
    l[idx] = __float2bfloat16(v - __bfloat162float(hv));
}

// flatten: (B,D,H,W) -> x fp32 + split, pos fp32, q=x+pos split
__global__ void flatten_kernel(const float* __restrict__ s0, const float* __restrict__ s1,
                               const float* __restrict__ s2, const float* __restrict__ s3,
                               const float* __restrict__ p0, const float* __restrict__ p1,
                               const float* __restrict__ p2, const float* __restrict__ p3,
                               const float* __restrict__ lenc,
                               float* __restrict__ x, float* __restrict__ pos,
                               bf16* __restrict__ xh, bf16* __restrict__ xl,
                               bf16* __restrict__ qh, bf16* __restrict__ ql)
{
    __shared__ float ts[32][33];
    __shared__ float tp[32][33];
    const int b  = blockIdx.z;
    const int q0 = blockIdx.x * 32;
    const int d0 = blockIdx.y * 32;

    int l, start, HW;
    const float *src, *pp;
    if (q0 < 4096)      { l = 0; start = 0;    HW = 4096; src = s0; pp = p0; }
    else if (q0 < 5120) { l = 1; start = 4096; HW = 1024; src = s1; pp = p1; }
    else if (q0 < 5376) { l = 2; start = 5120; HW = 256;  src = s2; pp = p2; }
    else                { l = 3; start = 5376; HW = 64;   src = s3; pp = p3; }

    const int pix0 = q0 - start;
    const int tx = threadIdx.x, ty = threadIdx.y;

    long sidx = ((long)b * DMODEL + (d0 + ty)) * HW + pix0 + tx;
    ts[ty][tx] = src[sidx];
    tp[ty][tx] = pp[sidx];
    __syncthreads();

    const int q  = q0 + ty;
    const int dd = d0 + tx;
    const size_t oidx = ((size_t)b * LQ + q) * DMODEL + dd;
    const float xv = ts[tx][ty];
    const float pv = tp[tx][ty] + lenc[l * DMODEL + dd];
    x[oidx]   = xv;
    pos[oidx] = pv;
    split_store(xh, xl, oidx, xv);
    split_store(qh, ql, oidx, xv + pv);
}

// deformable sampling + fused softmax; one warp per (b,q,h)
// tap-parallel: 4 tap-groups x 8 lanes, each lane holds 4 channels (float4)
__global__ void __launch_bounds__(256) sample_kernel(
    const float* __restrict__ val, const float* __restrict__ proj,
    bf16* __restrict__ acch, bf16* __restrict__ accl)
{
    const int gwid = (blockIdx.x * blockDim.x + threadIdx.x) >> 5;
    const int lane = threadIdx.x & 31;
    const int h = gwid % NH;
    const int q = (gwid / NH) % LQ;
    const int b = gwid / (NH * LQ);

    const size_t rowq = (size_t)b * LQ + q;
    const float* pr = proj + rowq * 384;

    // softmax over 16 logits (replicated to both warp halves)
    float lv = pr[256 + h * 16 + (lane & 15)];
    float mx = half_max16(lv);
    float e  = __expf(lv - mx);
    float s  = half_sum16(e);
    const float wgt = e / s;     // lane L holds weight of sample L & 15

    int W0, start0;
    if (q < 4096)      { W0 = 64; start0 = 0;    }
    else if (q < 5120) { W0 = 32; start0 = 4096; }
    else if (q < 5376) { W0 = 16; start0 = 5120; }
    else               { W0 = 8;  start0 = 5376; }
    const int pix = q - start0;
    const float refx = ((pix % W0) + 0.5f) / (float)W0;
    const float refy = ((pix / W0) + 0.5f) / (float)W0;

    const float* ob = pr + h * 32;
    const int tap = lane >> 3;         // 0..3: (x0,y0),(x0+1,y0),(x0,y0+1),(x0+1,y0+1)
    const int tdx = tap & 1, tdy = tap >> 1;
    const int ch4 = (lane & 7) * 4;

    const int Ls[4] = {64, 32, 16, 8};
    const int Ss[4] = {0, 4096, 5120, 5376};
    float4 a4 = make_float4(0.f, 0.f, 0.f, 0.f);

#pragma unroll
    for (int l = 0; l < NLVL; l++) {
        const int   HH = Ls[l];
        const float fH = (float)HH;
        const float* vb = val + ((size_t)b * LQ + Ss[l]) * (NH * DH) + h * DH + ch4;
#pragma unroll
        for (int p = 0; p < NPT; p++) {
            const int si = l * NPT + p;
            const float ox = ob[si * 2];
            const float oy = ob[si * 2 + 1];
            const float aw = __shfl_sync(0xffffffffu, wgt, si);
            const float xx = refx * fH + ox - 0.5f;
            const float yy = refy * fH + oy - 0.5f;
            const float xf = floorf(xx), yf = floorf(yy);
            const float dx = xx - xf, dy = yy - yf;
            const int xi = (int)xf + tdx;
            const int yi = (int)yf + tdy;
            const float wt = (tdx ? dx : 1.f - dx) * (tdy ? dy : 1.f - dy) * aw;
            if (xi >= 0 && xi < HH && yi >= 0 && yi < HH) {
                const float4 v = *(const float4*)(vb + (size_t)(yi * HH + xi) * (NH * DH));
                a4.x += wt * v.x; a4.y += wt * v.y;
                a4.z += wt * v.z; a4.w += wt * v.w;
            }
        }
    }
    // reduce the 4 tap-groups (linear: weights already folded in)
#pragma unroll
    for (int o = 8; o <= 16; o <<= 1) {
        a4.x += __shfl_xor_sync(0xffffffffu, a4.x, o);
        a4.y += __shfl_xor_sync(0xffffffffu, a4.y, o);
        a4.z += __shfl_xor_sync(0xffffffffu, a4.z, o);
        a4.w += __shfl_xor_sync(0xffffffffu, a4.w, o);
    }
    if (tap == 0) {
        const size_t oi = (rowq * NH + h) * DH + ch4;
        bf16 h0 = __float2bfloat16(a4.x), h1 = __float2bfloat16(a4.y);
        bf16 h2 = __float2bfloat16(a4.z), h3 = __float2bfloat16(a4.w);
        bf16 l0 = __float2bfloat16(a4.x - __bfloat162float(h0));
        bf16 l1 = __float2bfloat16(a4.y - __bfloat162float(h1));
        bf16 l2 = __float2bfloat16(a4.z - __bfloat162float(h2));
        bf16 l3 = __float2bfloat16(a4.w - __bfloat162float(h3));
        *(uint2*)(acch + oi) = make_uint2(b2u(__halves2bfloat162(h0, h1)),
                                          b2u(__halves2bfloat162(h2, h3)));
        *(uint2*)(accl + oi) = make_uint2(b2u(__halves2bfloat162(l0, l1)),
                                          b2u(__halves2bfloat162(l2, l3)));
    }
}

// fused residual-add + LayerNorm; optional split out; optional q=out+pos split
__global__ void __launch_bounds__(256) add_ln_kernel(
    const float* __restrict__ x, const float* __restrict__ r,
    const float* __restrict__ g, const float* __restrict__ bta,
    float* __restrict__ out,
    bf16* __restrict__ oh, bf16* __restrict__ ol,
    const float* __restrict__ pos,
    bf16* __restrict__ qh, bf16* __restrict__ ql,
    int flags)
{
    const int row  = blockIdx.x * 8 + (threadIdx.x >> 5);
    const int lane = threadIdx.x & 31;
    const size_t base = (size_t)row * DMODEL;
    const float* xr = x + base;
    const float* rr = r + base;

    float v[8];
    float sum = 0.f;
#pragma unroll
    for (int k = 0; k < 8; k++) {
        v[k] = xr[lane + 32 * k] + rr[lane + 32 * k];
        sum += v[k];
    }
    sum = warp_sum(sum);
    const float mu = sum * (1.f / 256.f);
    float vs = 0.f;
#pragma unroll
    for (int k = 0; k < 8; k++) { float d = v[k] - mu; vs += d * d; }
    vs = warp_sum(vs) * (1.f / 256.f);
    const float inv = rsqrtf(vs + 1e-5f);
#pragma unroll
    for (int k = 0; k < 8; k++) {
        const int c = lane + 32 * k;
        const float o = (v[k] - mu) * inv * g[c] + bta[c];
        out[base + c] = o;
        if (flags & 1) split_store(oh, ol, base + c, o);
        if (flags & 2) split_store(qh, ql, base + c, o + pos[base + c]);
    }
}

// ---------------- host orchestration ----------------
static void tcgemm(const bf16* Ah, const bf16* Al, const bf16* Bh, const bf16* Bl,
                   const float* bias, float* Cf, bf16* Ch, bf16* Cl,
                   int K, int N, int mode)
{
    dim3 grid(N / 128, MROWS / 128);
    mma_gemm<<<grid, 256, 2 * STG>>>(Ah, Al, Bh, Bl, bias, Cf, Ch, Cl, K, N, mode);
}

extern "C" void kernel_launch(void* const* d_in, const int* in_sizes, int n_in,
                              void* d_out, int out_size)
{
    cudaFuncSetAttribute(mma_gemm,  cudaFuncAttributeMaxDynamicSharedMemorySize, 2 * STG);
    cudaFuncSetAttribute(proj_gemm, cudaFuncAttributeMaxDynamicSharedMemorySize, 2 * STG);

    // inputs may arrive interleaved (src0,pos0,src1,pos1,...) per dict order
    const float* src[4];
    const float* pos[4];
    if (in_sizes[1] == in_sizes[0]) {
        for (int i = 0; i < 4; i++) {
            src[i] = (const float*)d_in[2 * i];
            pos[i] = (const float*)d_in[2 * i + 1];
        }
    } else {
        for (int i = 0; i < 4; i++) {
            src[i] = (const float*)d_in[i];
            pos[i] = (const float*)d_in[4 + i];
        }
    }
    const float* lenc  = (const float*)d_in[8];
    const float* Wv    = (const float*)d_in[9];
    const float* bv    = (const float*)d_in[10];
    const float* Wo    = (const float*)d_in[11];
    const float* bo    = (const float*)d_in[12];
    const float* Wa    = (const float*)d_in[13];
    const float* ba    = (const float*)d_in[14];
    const float* Wout  = (const float*)d_in[15];
    const float* bout  = (const float*)d_in[16];
    const float* ln1g  = (const float*)d_in[17];
    const float* ln1b  = (const float*)d_in[18];
    const float* W1    = (const float*)d_in[19];
    const float* b1    = (const float*)d_in[20];
    const float* W2    = (const float*)d_in[21];
    const float* b2    = (const float*)d_in[22];
    const float* ln2g  = (const float*)d_in[23];
    const float* ln2b  = (const float*)d_in[24];
    float* out = (float*)d_out;

    float *x, *posb, *vb, *ob, *tmpb, *boa;
    cudaGetSymbolAddress((void**)&x,    g_x);
    cudaGetSymbolAddress((void**)&posb, g_pos);
    cudaGetSymbolAddress((void**)&vb,   g_val);
    cudaGetSymbolAddress((void**)&ob,   g_off);
    cudaGetSymbolAddress((void**)&tmpb, g_tmp);
    cudaGetSymbolAddress((void**)&boa,  g_boa);

    bf16 *xh, *xl, *qh, *ql, *ach, *acl, *hh, *hl;
    cudaGetSymbolAddress((void**)&xh,  g_xh);  cudaGetSymbolAddress((void**)&xl,  g_xl);
    cudaGetSymbolAddress((void**)&qh,  g_qh);  cudaGetSymbolAddress((void**)&ql,  g_ql);
    cudaGetSymbolAddress((void**)&ach, g_ach); cudaGetSymbolAddress((void**)&acl, g_acl);
    cudaGetSymbolAddress((void**)&hh,  g_hh);  cudaGetSymbolAddress((void**)&hl,  g_hl);

    bf16 *wvh, *wvl, *woah, *woal, *wuh, *wul, *w1h, *w1l, *w2h, *w2l;
    cudaGetSymbolAddress((void**)&wvh,  g_wv_h);  cudaGetSymbolAddress((void**)&wvl,  g_wv_l);
    cudaGetSymbolAddress((void**)&woah, g_woa_h); cudaGetSymbolAddress((void**)&woal, g_woa_l);
    cudaGetSymbolAddress((void**)&wuh,  g_wu_h);  cudaGetSymbolAddress((void**)&wul,  g_wu_l);
    cudaGetSymbolAddress((void**)&w1h,  g_w1_h);  cudaGetSymbolAddress((void**)&w1l,  g_w1_l);
    cudaGetSymbolAddress((void**)&w2h,  g_w2_h);  cudaGetSymbolAddress((void**)&w2l,  g_w2_l);

    // launch 0: all weight transposes+splits; launch 1: bias pack
    {
        dim3 blk(32, 32);
        prep_kernel<<<4416, blk>>>(Wv, Wo, Wa, Wout, W1, W2,
                                   wvh, wvl, woah, woal, wuh, wul,
                                   w1h, w1l, w2h, w2l);
        bpack_kernel<<<NLAYERS, 384>>>(bo, ba, boa);
    }

    // launch 2: flatten inputs (+ x split, q split for layer 0)
    {
        dim3 grid(LQ / 32, DMODEL / 32, BATCH);
        dim3 blk(32, 32);
        flatten_kernel<<<grid, blk>>>(src[0], src[1], src[2], src[3],
                                      pos[0], pos[1], pos[2], pos[3],
                                      lenc, x, posb, xh, xl, qh, ql);
    }

    const int sample_blocks = (MROWS * NH * 32) / 256;
    const int ln_blocks = MROWS / 8;

    for (int i = 0; i < NLAYERS; i++) {
        const size_t o64k  = (size_t)i * 256 * 256;
        const size_t o96k  = (size_t)i * 384 * 256;
        const size_t o256k = (size_t)i * 1024 * 256;

        // fused: value = x@Wv + bv  ||  offsets+logits = q@[Wo|Wa] + [bo|ba]
        {
            dim3 grid(3, MROWS / 128, 2);
            proj_gemm<<<grid, 256, 2 * STG>>>(
                xh, xl, wvh + o64k, wvl + o64k, bv + (size_t)i * 256, vb,
                qh, ql, woah + o96k, woal + o96k, boa + (size_t)i * 384, ob);
        }
        // softmax + deformable sampling -> split bf16 acc
        sample_kernel<<<sample_blocks, 256>>>(vb, ob, ach, acl);
        // output projection
        tcgemm(ach, acl, wuh + o64k, wul + o64k, bout + (size_t)i * 256,
               tmpb, nullptr, nullptr, 256, 256, 0);
        // x = LN(x + attn); split for W1
        add_ln_kernel<<<ln_blocks, 256>>>(x, tmpb, ln1g + (size_t)i * 256,
                                          ln1b + (size_t)i * 256, x,
                                          xh, xl, nullptr, nullptr, nullptr, 1);
        // FFN: h = relu(x @ W1 + b1) -> split bf16
        tcgemm(xh, xl, w1h + o256k, w1l + o256k, b1 + (size_t)i * 1024,
               nullptr, hh, hl, 256, 1024, 1);
        tcgemm(hh, hl, w2h + o256k, w2l + o256k, b2 + (size_t)i * 256,
               tmpb, nullptr, nullptr, 1024, 256, 0);
        // x = LN(x + ffn); split x for next Wv; q = x + pos split for next layer
        const int last = (i == NLAYERS - 1);
        add_ln_kernel<<<ln_blocks, 256>>>(x, tmpb, ln2g + (size_t)i * 256,
                                          ln2b + (size_t)i * 256,
                                          last ? out : x,
                                          xh, xl, posb, qh, ql, last ? 0 : 3);
    }
}

// round 8
// speedup vs baseline: 2.5497x; 1.1898x over previous
#include <cuda_runtime.h>
#include <cuda_fp16.h>
#include <cstdint>

// ---------------- problem constants ----------------
#define BATCH   8
#define DMODEL  256
#define NH      8
#define NLVL    4
#define NPT     4
#define DH      32
#define NLAYERS 6
#define DFF     1024
#define LQ      5440            // 4096 + 1024 + 256 + 64
#define MROWS   (BATCH * LQ)    // 43520

typedef __half f16;

// ---------------- scratch (device globals; no allocation allowed) ----------------
__device__ __align__(16) float g_x   [MROWS * DMODEL];
__device__ __align__(16) float g_pos [MROWS * DMODEL];
__device__ __align__(16) float g_val [MROWS * DMODEL];
__device__ __align__(16) float g_off [MROWS * 384];     // offsets(256)+logits(128)
__device__ __align__(16) float g_tmp [MROWS * DMODEL];

__device__ __align__(16) f16 g_xh [MROWS * DMODEL];
__device__ __align__(16) f16 g_xl [MROWS * DMODEL];
__device__ __align__(16) f16 g_qh [MROWS * DMODEL];
__device__ __align__(16) f16 g_ql [MROWS * DMODEL];
__device__ __align__(16) f16 g_ach[MROWS * DMODEL];
__device__ __align__(16) f16 g_acl[MROWS * DMODEL];
__device__ __align__(16) f16 g_hh [MROWS * DFF];
__device__ __align__(16) f16 g_hl [MROWS * DFF];

// fp16 weights (hi only), transposed to [N, K] K-major
__device__ __align__(16) f16 g_wv_h [NLAYERS * 256 * 256];
__device__ __align__(16) f16 g_woa_h[NLAYERS * 384 * 256];   // Wo rows 0-255, Wa rows 256-383
__device__ __align__(16) f16 g_wu_h [NLAYERS * 256 * 256];
__device__ __align__(16) f16 g_w1_h [NLAYERS * 1024 * 256];
__device__ __align__(16) f16 g_w2_h [NLAYERS * 256 * 1024];
__device__ __align__(16) float g_boa [NLAYERS * 384];

// ---------------- low-level helpers ----------------
__device__ __forceinline__ uint32_t smem_u32(const void* p) {
    uint32_t a;
    asm("{ .reg .u64 t; cvta.to.shared.u64 t, %1; cvt.u32.u64 %0, t; }"
        : "=r"(a) : "l"(p));
    return a;
}
__device__ __forceinline__ void ldm4(uint32_t* r, uint32_t addr) {
    asm volatile("ldmatrix.sync.aligned.m8n8.x4.shared.b16 {%0,%1,%2,%3}, [%4];"
                 : "=r"(r[0]), "=r"(r[1]), "=r"(r[2]), "=r"(r[3]) : "r"(addr));
}
__device__ __forceinline__ void mma16816(float* c, const uint32_t* a,
                                         const uint32_t* b) {
    asm volatile(
        "mma.sync.aligned.m16n8k16.row.col.f32.f16.f16.f32 "
        "{%0,%1,%2,%3}, {%4,%5,%6,%7}, {%8,%9}, {%0,%1,%2,%3};"
        : "+f"(c[0]), "+f"(c[1]), "+f"(c[2]), "+f"(c[3])
        : "r"(a[0]), "r"(a[1]), "r"(a[2]), "r"(a[3]), "r"(b[0]), "r"(b[1]));
}
__device__ __forceinline__ uint32_t h2u(__half2 v) {
    return *reinterpret_cast<uint32_t*>(&v);
}
#define CP_ASYNC16(d, s) \
    asm volatile("cp.async.cg.shared.global [%0], [%1], 16;" :: "r"(d), "l"(s))
#define CP_COMMIT() asm volatile("cp.async.commit_group;" ::: "memory")
#define CP_WAIT(n)  asm volatile("cp.async.wait_group %0;" :: "n"(n) : "memory")

// ---------------- merged weight prep: all transposes + fp16 rounding, ONE launch --
__global__ void prep_kernel(
    const float* __restrict__ Wv, const float* __restrict__ Wo,
    const float* __restrict__ Wa, const float* __restrict__ Wout,
    const float* __restrict__ W1, const float* __restrict__ W2,
    f16* __restrict__ wvh, f16* __restrict__ woah, f16* __restrict__ wuh,
    f16* __restrict__ w1h, f16* __restrict__ w2h)
{
    __shared__ float t[32][33];
    int bid = blockIdx.x;
    const float* W; f16* hi;
    int K, N, Ntot, rowoff, tpl;
    if (bid < 384)       { W = Wv;   hi = wvh;  K = 256;  N = 256;  Ntot = 256;  rowoff = 0;   tpl = 64;  }
    else if (bid < 768)  { bid -= 384;  W = Wo;   hi = woah; K = 256;  N = 256;  Ntot = 384;  rowoff = 0;   tpl = 64;  }
    else if (bid < 960)  { bid -= 768;  W = Wa;   hi = woah; K = 256;  N = 128;  Ntot = 384;  rowoff = 256; tpl = 32;  }
    else if (bid < 1344) { bid -= 960;  W = Wout; hi = wuh;  K = 256;  N = 256;  Ntot = 256;  rowoff = 0;   tpl = 64;  }
    else if (bid < 2880) { bid -= 1344; W = W1;   hi = w1h;  K = 256;  N = 1024; Ntot = 1024; rowoff = 0;   tpl = 256; }
    else                 { bid -= 2880; W = W2;   hi = w2h;  K = 1024; N = 256;  Ntot = 256;  rowoff = 0;   tpl = 256; }
    const int l = bid / tpl, tt = bid % tpl;
    const int nt = N / 32;
    const int n0 = (tt % nt) * 32, k0 = (tt / nt) * 32;

    const float* Wl = W + (size_t)l * K * N;
    t[threadIdx.y][threadIdx.x] = Wl[(size_t)(k0 + threadIdx.y) * N + n0 + threadIdx.x];
    __syncthreads();
    const size_t o = ((size_t)l * Ntot + rowoff + n0 + threadIdx.y) * K + k0 + threadIdx.x;
    hi[o] = __float2half_rn(t[threadIdx.x][threadIdx.y]);
}

__global__ void bpack_kernel(const float* __restrict__ bo, const float* __restrict__ ba,
                             float* __restrict__ boa)
{
    const int l = blockIdx.x, t = threadIdx.x;   // 384 threads
    boa[l * 384 + t] = (t < 256) ? bo[l * 256 + t] : ba[l * 128 + (t - 256)];
}

// ---------------- pipelined split-fp16 mma.sync GEMM core ----------------
// C = (Ah+Al)[M,K] @ Bh[N,K]^T + bias  (2 passes: AhBh + AlBh)
// CTA 128x128, 8 warps 2x4, warp tile 64x32, BK=32, cp.async 3-stage.
#define GPITCH 80
#define TILESZ 10240
#define STGSZ  30720   // Ah + Al + Bh

__device__ __forceinline__ void gemm_core(
    const f16* __restrict__ Ah, const f16* __restrict__ Al,
    const f16* __restrict__ Bh,
    const float* __restrict__ bias, float* __restrict__ Cf,
    f16* __restrict__ Ch, f16* __restrict__ Cl,
    int K, int N, int mode, int m0, int n0, uint8_t* sm)
{
    const uint32_t sb = smem_u32(sm);
    const int tid = threadIdx.x;
    const int wid = tid >> 5, lane = tid & 31;
    const int wm = wid >> 2, wn = wid & 3;
    const int m0w = wm * 64, n0w = wn * 32;
    const int tlq = lane >> 3, rlq = lane & 7;

    const f16* gb[3] = {Ah + (size_t)m0 * K, Al + (size_t)m0 * K,
                        Bh + (size_t)n0 * K};

    float acc[4][4][4];
#pragma unroll
    for (int i = 0; i < 4; i++)
#pragma unroll
        for (int j = 0; j < 4; j++)
#pragma unroll
            for (int c = 0; c < 4; c++) acc[i][j][c] = 0.f;

    const int nchunk = K >> 5;

    auto docopy = [&](int ch) {
        const int k0 = ch << 5;
        const uint32_t sbase = sb + (uint32_t)(ch % 3) * STGSZ;
#pragma unroll
        for (int j = 0; j < 6; j++) {
            const int buf = j >> 1;
            const int s = tid + ((j & 1) << 8);
            const int row = s >> 2, seg = s & 3;
            const f16* g = gb[buf] + (size_t)row * K + k0 + seg * 8;
            const uint32_t d = sbase + buf * TILESZ + row * GPITCH + seg * 16;
            CP_ASYNC16(d, g);
        }
        CP_COMMIT();
    };

    docopy(0);
    if (nchunk > 1) docopy(1);
    for (int ch = 0; ch < nchunk; ch++) {
        if (ch + 2 < nchunk) { docopy(ch + 2); CP_WAIT(2); }
        else if (ch + 1 < nchunk) { CP_WAIT(1); }
        else { CP_WAIT(0); }
        __syncthreads();

        const uint32_t soff = sb + (uint32_t)(ch % 3) * STGSZ;
#pragma unroll
        for (int ks = 0; ks < 2; ks++) {
            const int kk = ks * 16;
            uint32_t af[16], bfr[8];

            // A hi fragments
#pragma unroll
            for (int mi = 0; mi < 4; mi++) {
                const int r = m0w + mi * 16 + rlq + ((tlq & 1) << 3);
                const int kc = kk + ((tlq >> 1) << 3);
                ldm4(af + mi * 4, soff + r * GPITCH + kc * 2);
            }
            // B fragments
#pragma unroll
            for (int nj = 0; nj < 2; nj++) {
                const int r = n0w + nj * 16 + rlq + ((tlq >> 1) << 3);
                const int kc = kk + ((tlq & 1) << 3);
                ldm4(bfr + nj * 4, soff + 2 * TILESZ + r * GPITCH + kc * 2);
            }
            // pass 1: Ah*Bh
#pragma unroll
            for (int mi = 0; mi < 4; mi++)
#pragma unroll
                for (int ni = 0; ni < 4; ni++) {
                    uint32_t b2r[2] = {bfr[(ni >> 1) * 4 + (ni & 1) * 2],
                                       bfr[(ni >> 1) * 4 + (ni & 1) * 2 + 1]};
                    mma16816(acc[mi][ni], af + mi * 4, b2r);
                }
            // A lo fragments
#pragma unroll
            for (int mi = 0; mi < 4; mi++) {
                const int r = m0w + mi * 16 + rlq + ((tlq & 1) << 3);
                const int kc = kk + ((tlq >> 1) << 3);
                ldm4(af + mi * 4, soff + TILESZ + r * GPITCH + kc * 2);
            }
            // pass 2: Al*Bh
#pragma unroll
            for (int mi = 0; mi < 4; mi++)
#pragma unroll
                for (int ni = 0; ni < 4; ni++) {
                    uint32_t b2r[2] = {bfr[(ni >> 1) * 4 + (ni & 1) * 2],
                                       bfr[(ni >> 1) * 4 + (ni & 1) * 2 + 1]};
                    mma16816(acc[mi][ni], af + mi * 4, b2r);
                }
        }
        __syncthreads();
    }

    const int g = lane >> 2, tg = lane & 3;
#pragma unroll
    for (int mi = 0; mi < 4; mi++) {
        const int r0 = m0 + m0w + mi * 16 + g;
#pragma unroll
        for (int ni = 0; ni < 4; ni++) {
            const int col = n0 + n0w + ni * 8 + tg * 2;
            const float b0 = bias[col], b1 = bias[col + 1];
            float v00 = acc[mi][ni][0] + b0, v01 = acc[mi][ni][1] + b1;
            float v10 = acc[mi][ni][2] + b0, v11 = acc[mi][ni][3] + b1;
            if (mode == 0) {
                *(float2*)(Cf + (size_t)r0 * N + col)       = make_float2(v00, v01);
                *(float2*)(Cf + (size_t)(r0 + 8) * N + col) = make_float2(v10, v11);
            } else {
                v00 = fmaxf(v00, 0.f); v01 = fmaxf(v01, 0.f);
                v10 = fmaxf(v10, 0.f); v11 = fmaxf(v11, 0.f);
                f16 h00 = __float2half_rn(v00), h01 = __float2half_rn(v01);
                f16 h10 = __float2half_rn(v10), h11 = __float2half_rn(v11);
                f16 l00 = __float2half_rn(v00 - __half2float(h00));
                f16 l01 = __float2half_rn(v01 - __half2float(h01));
                f16 l10 = __float2half_rn(v10 - __half2float(h10));
                f16 l11 = __float2half_rn(v11 - __half2float(h11));
                *(uint32_t*)(Ch + (size_t)r0 * N + col)       = h2u(__halves2half2(h00, h01));
                *(uint32_t*)(Cl + (size_t)r0 * N + col)       = h2u(__halves2half2(l00, l01));
                *(uint32_t*)(Ch + (size_t)(r0 + 8) * N + col) = h2u(__halves2half2(h10, h11));
                *(uint32_t*)(Cl + (size_t)(r0 + 8) * N + col) = h2u(__halves2half2(l10, l11));
            }
        }
    }
}

__global__ void __launch_bounds__(256, 2) mma_gemm(
    const f16* __restrict__ Ah, const f16* __restrict__ Al,
    const f16* __restrict__ Bh,
    const float* __restrict__ bias, float* __restrict__ Cf,
    f16* __restrict__ Ch, f16* __restrict__ Cl,
    int K, int N, int mode)
{
    extern __shared__ __align__(16) uint8_t sm[];
    gemm_core(Ah, Al, Bh, bias, Cf, Ch, Cl, K, N, mode,
              blockIdx.y * 128, blockIdx.x * 128, sm);
}

// fused value + offsets/logits projections (independent, share a launch)
__global__ void __launch_bounds__(256, 2) proj_gemm(
    const f16* __restrict__ xh, const f16* __restrict__ xl,
    const f16* __restrict__ wvh,
    const float* __restrict__ bv, float* __restrict__ vb,
    const f16* __restrict__ qh, const f16* __restrict__ ql,
    const f16* __restrict__ woah,
    const float* __restrict__ boa, float* __restrict__ ob)
{
    extern __shared__ __align__(16) uint8_t sm[];
    const int m0 = blockIdx.y * 128, n0 = blockIdx.x * 128;
    if (blockIdx.z == 0) {
        if (blockIdx.x >= 2) return;
        gemm_core(xh, xl, wvh, bv, vb, nullptr, nullptr, 256, 256, 0, m0, n0, sm);
    } else {
        gemm_core(qh, ql, woah, boa, ob, nullptr, nullptr, 256, 384, 0, m0, n0, sm);
    }
}

// ---------------- non-GEMM kernels ----------------
__device__ __forceinline__ float warp_sum(float v) {
#pragma unroll
    for (int o = 16; o > 0; o >>= 1) v += __shfl_xor_sync(0xffffffffu, v, o);
    return v;
}
__device__ __forceinline__ float half_sum16(float v) {
#pragma unroll
    for (int o = 8; o > 0; o >>= 1) v += __shfl_xor_sync(0xffffffffu, v, o);
    return v;
}
__device__ __forceinline__ float half_max16(float v) {
#pragma unroll
    for (int o = 8; o > 0; o >>= 1) v = fmaxf(v, __shfl_xor_sync(0xffffffffu, v, o));
    return v;
}
__device__ __forceinline__ void split_store(f16* h, f16* l, size_t idx, float v) {
    f16 hv = __float2half_rn(v);
    h[idx] = hv;
    l[idx] = __float2half_rn(v - __half2float(hv));
}

// flatten: (B,D,H,W) -> x fp32, pos fp32, x split, q=x+pos split
__global__ void flatten_kernel(const float* __restrict__ s0, const float* __restrict__ s1,
                               const float* __restrict__ s2, const float* __restrict__ s3,
                               const float* __restrict__ p0, const float* __restrict__ p1,
                               const float* __restrict__ p2, const float* __restrict__ p3,
                               const float* __restrict__ lenc,
                               float* __restrict__ x, float* __restrict__ pos,
                               f16* __restrict__ xh, f16* __restrict__ xl,
                               f16* __restrict__ qh, f16* __restrict__ ql)
{
    __shared__ float ts[32][33];
    __shared__ float tp[32][33];
    const int b  = blockIdx.z;
    const int q0 = blockIdx.x * 32;
    const int d0 = blockIdx.y * 32;

    int l, start, HW;
    const float *src, *pp;
    if (q0 < 4096)      { l = 0; start = 0;    HW = 4096; src = s0; pp = p0; }
    else if (q0 < 5120) { l = 1; start = 4096; HW = 1024; src = s1; pp = p1; }
    else if (q0 < 5376) { l = 2; start = 5120; HW = 256;  src = s2; pp = p2; }
    else                { l = 3; start = 5376; HW = 64;   src = s3; pp = p3; }

    const int pix0 = q0 - start;
    const int tx = threadIdx.x, ty = threadIdx.y;

    long sidx = ((long)b * DMODEL + (d0 + ty)) * HW + pix0 + tx;
    ts[ty][tx] = src[sidx];
    tp[ty][tx] = pp[sidx];
    __syncthreads();

    const int q  = q0 + ty;
    const int dd = d0 + tx;
    const size_t oidx = ((size_t)b * LQ + q) * DMODEL + dd;
    const float xv = ts[tx][ty];
    const float pv = tp[tx][ty] + lenc[l * DMODEL + dd];
    x[oidx]   = xv;
    pos[oidx] = pv;
    split_store(xh, xl, oidx, xv);
    split_store(qh, ql, oidx, xv + pv);
}

// deformable sampling + fused softmax; one warp per (b,q,h)
// tap-parallel: 4 tap-groups x 8 lanes, each lane holds 4 channels (float4)
__global__ void __launch_bounds__(256) sample_kernel(
    const float* __restrict__ val, const float* __restrict__ proj,
    f16* __restrict__ acch, f16* __restrict__ accl)
{
    const int gwid = (blockIdx.x * blockDim.x + threadIdx.x) >> 5;
    const int lane = threadIdx.x & 31;
    const int h = gwid % NH;
    const int q = (gwid / NH) % LQ;
    const int b = gwid / (NH * LQ);

    const size_t rowq = (size_t)b * LQ + q;
    const float* pr = proj + rowq * 384;

    float lv = pr[256 + h * 16 + (lane & 15)];
    float mx = half_max16(lv);
    float e  = __expf(lv - mx);
    float s  = half_sum16(e);
    const float wgt = e / s;

    int W0, start0;
    if (q < 4096)      { W0 = 64; start0 = 0;    }
    else if (q < 5120) { W0 = 32; start0 = 4096; }
    else if (q < 5376) { W0 = 16; start0 = 5120; }
    else               { W0 = 8;  start0 = 5376; }
    const int pix = q - start0;
    const float refx = ((pix % W0) + 0.5f) / (float)W0;
    const float refy = ((pix / W0) + 0.5f) / (float)W0;

    const float* ob = pr + h * 32;
    const int tap = lane >> 3;
    const int tdx = tap & 1, tdy = tap >> 1;
    const int ch4 = (lane & 7) * 4;

    const int Ls[4] = {64, 32, 16, 8};
    const int Ss[4] = {0, 4096, 5120, 5376};
    float4 a4 = make_float4(0.f, 0.f, 0.f, 0.f);

#pragma unroll
    for (int l = 0; l < NLVL; l++) {
        const int   HH = Ls[l];
        const float fH = (float)HH;
        const float* vb = val + ((size_t)b * LQ + Ss[l]) * (NH * DH) + h * DH + ch4;
#pragma unroll
        for (int p = 0; p < NPT; p++) {
            const int si = l * NPT + p;
            const float ox = ob[si * 2];
            const float oy = ob[si * 2 + 1];
            const float aw = __shfl_sync(0xffffffffu, wgt, si);
            const float xx = refx * fH + ox - 0.5f;
            const float yy = refy * fH + oy - 0.5f;
            const float xf = floorf(xx), yf = floorf(yy);
            const float dx = xx - xf, dy = yy - yf;
            const int xi = (int)xf + tdx;
            const int yi = (int)yf + tdy;
            const float wt = (tdx ? dx : 1.f - dx) * (tdy ? dy : 1.f - dy) * aw;
            if (xi >= 0 && xi < HH && yi >= 0 && yi < HH) {
                const float4 v = *(const float4*)(vb + (size_t)(yi * HH + xi) * (NH * DH));
                a4.x += wt * v.x; a4.y += wt * v.y;
                a4.z += wt * v.z; a4.w += wt * v.w;
            }
        }
    }
#pragma unroll
    for (int o = 8; o <= 16; o <<= 1) {
        a4.x += __shfl_xor_sync(0xffffffffu, a4.x, o);
        a4.y += __shfl_xor_sync(0xffffffffu, a4.y, o);
        a4.z += __shfl_xor_sync(0xffffffffu, a4.z, o);
        a4.w += __shfl_xor_sync(0xffffffffu, a4.w, o);
    }
    if (tap == 0) {
        const size_t oi = (rowq * NH + h) * DH + ch4;
        f16 h0 = __float2half_rn(a4.x), h1 = __float2half_rn(a4.y);
        f16 h2 = __float2half_rn(a4.z), h3 = __float2half_rn(a4.w);
        f16 l0 = __float2half_rn(a4.x - __half2float(h0));
        f16 l1 = __float2half_rn(a4.y - __half2float(h1));
        f16 l2 = __float2half_rn(a4.z - __half2float(h2));
        f16 l3 = __float2half_rn(a4.w - __half2float(h3));
        *(uint2*)(acch + oi) = make_uint2(h2u(__halves2half2(h0, h1)),
                                          h2u(__halves2half2(h2, h3)));
        *(uint2*)(accl + oi) = make_uint2(h2u(__halves2half2(l0, l1)),
                                          h2u(__halves2half2(l2, l3)));
    }
}

// fused residual-add + LayerNorm; optional split out; optional q=out+pos split
__global__ void __launch_bounds__(256) add_ln_kernel(
    const float* __restrict__ x, const float* __restrict__ r,
    const float* __restrict__ g, const float* __restrict__ bta,
    float* __restrict__ out,
    f16* __restrict__ oh, f16* __restrict__ ol,
    const float* __restrict__ pos,
    f16* __restrict__ qh, f16* __restrict__ ql,
    int flags)
{
    const int row  = blockIdx.x * 8 + (threadIdx.x >> 5);
    const int lane = threadIdx.x & 31;
    const size_t base = (size_t)row * DMODEL;
    const float* xr = x + base;
    const float* rr = r + base;

    float v[8];
    float sum = 0.f;
#pragma unroll
    for (int k = 0; k < 8; k++) {
        v[k] = xr[lane + 32 * k] + rr[lane + 32 * k];
        sum += v[k];
    }
    sum = warp_sum(sum);
    const float mu = sum * (1.f / 256.f);
    float vs = 0.f;
#pragma unroll
    for (int k = 0; k < 8; k++) { float d = v[k] - mu; vs += d * d; }
    vs = warp_sum(vs) * (1.f / 256.f);
    const float inv = rsqrtf(vs + 1e-5f);
#pragma unroll
    for (int k = 0; k < 8; k++) {
        const int c = lane + 32 * k;
        const float o = (v[k] - mu) * inv * g[c] + bta[c];
        out[base + c] = o;
        if (flags & 1) split_store(oh, ol, base + c, o);
        if (flags & 2) split_store(qh, ql, base + c, o + pos[base + c]);
    }
}

// ---------------- host orchestration ----------------
#define SMEM_GEMM (3 * STGSZ)

static void tcgemm(const f16* Ah, const f16* Al, const f16* Bh,
                   const float* bias, float* Cf, f16* Ch, f16* Cl,
                   int K, int N, int mode)
{
    dim3 grid(N / 128, MROWS / 128);
    mma_gemm<<<grid, 256, SMEM_GEMM>>>(Ah, Al, Bh, bias, Cf, Ch, Cl, K, N, mode);
}

extern "C" void kernel_launch(void* const* d_in, const int* in_sizes, int n_in,
                              void* d_out, int out_size)
{
    cudaFuncSetAttribute(mma_gemm,  cudaFuncAttributeMaxDynamicSharedMemorySize, SMEM_GEMM);
    cudaFuncSetAttribute(proj_gemm, cudaFuncAttributeMaxDynamicSharedMemorySize, SMEM_GEMM);

    // inputs may arrive interleaved (src0,pos0,src1,pos1,...) per dict order
    const float* src[4];
    const float* pos[4];
    if (in_sizes[1] == in_sizes[0]) {
        for (int i = 0; i < 4; i++) {
            src[i] = (const float*)d_in[2 * i];
            pos[i] = (const float*)d_in[2 * i + 1];
        }
    } else {
        for (int i = 0; i < 4; i++) {
            src[i] = (const float*)d_in[i];
            pos[i] = (const float*)d_in[4 + i];
        }
    }
    const float* lenc  = (const float*)d_in[8];
    const float* Wv    = (const float*)d_in[9];
    const float* bv    = (const float*)d_in[10];
    const float* Wo    = (const float*)d_in[11];
    const float* bo    = (const float*)d_in[12];
    const float* Wa    = (const float*)d_in[13];
    const float* ba    = (const float*)d_in[14];
    const float* Wout  = (const float*)d_in[15];
    const float* bout  = (const float*)d_in[16];
    const float* ln1g  = (const float*)d_in[17];
    const float* ln1b  = (const float*)d_in[18];
    const float* W1    = (const float*)d_in[19];
    const float* b1    = (const float*)d_in[20];
    const float* W2    = (const float*)d_in[21];
    const float* b2    = (const float*)d_in[22];
    const float* ln2g  = (const float*)d_in[23];
    const float* ln2b  = (const float*)d_in[24];
    float* out = (float*)d_out;

    float *x, *posb, *vb, *ob, *tmpb, *boa;
    cudaGetSymbolAddress((void**)&x,    g_x);
    cudaGetSymbolAddress((void**)&posb, g_pos);
    cudaGetSymbolAddress((void**)&vb,   g_val);
    cudaGetSymbolAddress((void**)&ob,   g_off);
    cudaGetSymbolAddress((void**)&tmpb, g_tmp);
    cudaGetSymbolAddress((void**)&boa,  g_boa);

    f16 *xh, *xl, *qh, *ql, *ach, *acl, *hh, *hl;
    cudaGetSymbolAddress((void**)&xh,  g_xh);  cudaGetSymbolAddress((void**)&xl,  g_xl);
    cudaGetSymbolAddress((void**)&qh,  g_qh);  cudaGetSymbolAddress((void**)&ql,  g_ql);
    cudaGetSymbolAddress((void**)&ach, g_ach); cudaGetSymbolAddress((void**)&acl, g_acl);
    cudaGetSymbolAddress((void**)&hh,  g_hh);  cudaGetSymbolAddress((void**)&hl,  g_hl);

    f16 *wvh, *woah, *wuh, *w1h, *w2h;
    cudaGetSymbolAddress((void**)&wvh,  g_wv_h);
    cudaGetSymbolAddress((void**)&woah, g_woa_h);
    cudaGetSymbolAddress((void**)&wuh,  g_wu_h);
    cudaGetSymbolAddress((void**)&w1h,  g_w1_h);
    cudaGetSymbolAddress((void**)&w2h,  g_w2_h);

    // launch 0: all weight transposes + fp16; launch 1: bias pack
    {
        dim3 blk(32, 32);
        prep_kernel<<<4416, blk>>>(Wv, Wo, Wa, Wout, W1, W2,
                                   wvh, woah, wuh, w1h, w2h);
        bpack_kernel<<<NLAYERS, 384>>>(bo, ba, boa);
    }

    // launch 2: flatten inputs (+ x split, q split for layer 0)
    {
        dim3 grid(LQ / 32, DMODEL / 32, BATCH);
        dim3 blk(32, 32);
        flatten_kernel<<<grid, blk>>>(src[0], src[1], src[2], src[3],
                                      pos[0], pos[1], pos[2], pos[3],
                                      lenc, x, posb, xh, xl, qh, ql);
    }

    const int sample_blocks = (MROWS * NH * 32) / 256;
    const int ln_blocks = MROWS / 8;

    for (int i = 0; i < NLAYERS; i++) {
        const size_t o64k  = (size_t)i * 256 * 256;
        const size_t o96k  = (size_t)i * 384 * 256;
        const size_t o256k = (size_t)i * 1024 * 256;

        // fused: value = x@Wv + bv  ||  offsets+logits = q@[Wo|Wa] + [bo|ba]
        {
            dim3 grid(3, MROWS / 128, 2);
            proj_gemm<<<grid, 256, SMEM_GEMM>>>(
                xh, xl, wvh + o64k, bv + (size_t)i * 256, vb,
                qh, ql, woah + o96k, boa + (size_t)i * 384, ob);
        }
        // softmax + deformable sampling -> split fp16 acc
        sample_kernel<<<sample_blocks, 256>>>(vb, ob, ach, acl);
        // output projection
        tcgemm(ach, acl, wuh + o64k, bout + (size_t)i * 256,
               tmpb, nullptr, nullptr, 256, 256, 0);
        // x = LN(x + attn); split for W1
        add_ln_kernel<<<ln_blocks, 256>>>(x, tmpb, ln1g + (size_t)i * 256,
                                          ln1b + (size_t)i * 256, x,
                                          xh, xl, nullptr, nullptr, nullptr, 1);
        // FFN: h = relu(x @ W1 + b1) -> split fp16
        tcgemm(xh, xl, w1h + o256k, b1 + (size_t)i * 1024,
               nullptr, hh, hl, 256, 1024, 1);
        tcgemm(hh, hl, w2h + o256k, b2 + (size_t)i * 256,
               tmpb, nullptr, nullptr, 1024, 256, 0);
        // x = LN(x + ffn); split x for next Wv; q = x + pos split for next layer
        const int last = (i == NLAYERS - 1);
        add_ln_kernel<<<ln_blocks, 256>>>(x, tmpb, ln2g + (size_t)i * 256,
                                          ln2b + (size_t)i * 256,
                                          last ? out : x,
                                          xh, xl, posb, qh, ql, last ? 0 : 3);
    }
}

// round 9
// speedup vs baseline: 3.4464x; 1.3517x over previous
#include <cuda_runtime.h>
#include <cuda_fp16.h>
#include <cstdint>

// ---------------- problem constants ----------------
#define BATCH   8
#define DMODEL  256
#define NH      8
#define NLVL    4
#define NPT     4
#define DH      32
#define NLAYERS 6
#define DFF     1024
#define LQ      5440            // 4096 + 1024 + 256 + 64
#define MROWS   (BATCH * LQ)    // 43520

typedef __half f16;

// ---------------- scratch (device globals; no allocation allowed) ----------------
__device__ __align__(16) float g_x   [MROWS * DMODEL];
__device__ __align__(16) float g_pos [MROWS * DMODEL];
__device__ __align__(16) float g_val [MROWS * DMODEL];
__device__ __align__(16) float g_off [MROWS * 384];     // offsets(256)+logits(128)
__device__ __align__(16) float g_tmp [MROWS * DMODEL];

__device__ __align__(16) f16 g_xh [MROWS * DMODEL];
__device__ __align__(16) f16 g_qh [MROWS * DMODEL];
__device__ __align__(16) f16 g_ach[MROWS * DMODEL];
__device__ __align__(16) f16 g_hh [MROWS * DFF];

// fp16 weights, transposed to [N, K] K-major
__device__ __align__(16) f16 g_wv_h [NLAYERS * 256 * 256];
__device__ __align__(16) f16 g_woa_h[NLAYERS * 384 * 256];   // Wo rows 0-255, Wa rows 256-383
__device__ __align__(16) f16 g_wu_h [NLAYERS * 256 * 256];
__device__ __align__(16) f16 g_w1_h [NLAYERS * 1024 * 256];
__device__ __align__(16) f16 g_w2_h [NLAYERS * 256 * 1024];
__device__ __align__(16) float g_boa [NLAYERS * 384];

// ---------------- low-level helpers ----------------
__device__ __forceinline__ uint32_t smem_u32(const void* p) {
    uint32_t a;
    asm("{ .reg .u64 t; cvta.to.shared.u64 t, %1; cvt.u32.u64 %0, t; }"
        : "=r"(a) : "l"(p));
    return a;
}
__device__ __forceinline__ void ldm4(uint32_t* r, uint32_t addr) {
    asm volatile("ldmatrix.sync.aligned.m8n8.x4.shared.b16 {%0,%1,%2,%3}, [%4];"
                 : "=r"(r[0]), "=r"(r[1]), "=r"(r[2]), "=r"(r[3]) : "r"(addr));
}
__device__ __forceinline__ void mma16816(float* c, const uint32_t* a,
                                         const uint32_t* b) {
    asm volatile(
        "mma.sync.aligned.m16n8k16.row.col.f32.f16.f16.f32 "
        "{%0,%1,%2,%3}, {%4,%5,%6,%7}, {%8,%9}, {%0,%1,%2,%3};"
        : "+f"(c[0]), "+f"(c[1]), "+f"(c[2]), "+f"(c[3])
        : "r"(a[0]), "r"(a[1]), "r"(a[2]), "r"(a[3]), "r"(b[0]), "r"(b[1]));
}
__device__ __forceinline__ uint32_t h2u(__half2 v) {
    return *reinterpret_cast<uint32_t*>(&v);
}
#define CP_ASYNC16(d, s) \
    asm volatile("cp.async.cg.shared.global [%0], [%1], 16;" :: "r"(d), "l"(s))
#define CP_COMMIT() asm volatile("cp.async.commit_group;" ::: "memory")
#define CP_WAIT(n)  asm volatile("cp.async.wait_group %0;" :: "n"(n) : "memory")

// ---------------- merged weight prep ----------------
__global__ void prep_kernel(
    const float* __restrict__ Wv, const float* __restrict__ Wo,
    const float* __restrict__ Wa, const float* __restrict__ Wout,
    const float* __restrict__ W1, const float* __restrict__ W2,
    f16* __restrict__ wvh, f16* __restrict__ woah, f16* __restrict__ wuh,
    f16* __restrict__ w1h, f16* __restrict__ w2h)
{
    __shared__ float t[32][33];
    int bid = blockIdx.x;
    const float* W; f16* hi;
    int K, N, Ntot, rowoff, tpl;
    if (bid < 384)       { W = Wv;   hi = wvh;  K = 256;  N = 256;  Ntot = 256;  rowoff = 0;   tpl = 64;  }
    else if (bid < 768)  { bid -= 384;  W = Wo;   hi = woah; K = 256;  N = 256;  Ntot = 384;  rowoff = 0;   tpl = 64;  }
    else if (bid < 960)  { bid -= 768;  W = Wa;   hi = woah; K = 256;  N = 128;  Ntot = 384;  rowoff = 256; tpl = 32;  }
    else if (bid < 1344) { bid -= 960;  W = Wout; hi = wuh;  K = 256;  N = 256;  Ntot = 256;  rowoff = 0;   tpl = 64;  }
    else if (bid < 2880) { bid -= 1344; W = W1;   hi = w1h;  K = 256;  N = 1024; Ntot = 1024; rowoff = 0;   tpl = 256; }
    else                 { bid -= 2880; W = W2;   hi = w2h;  K = 1024; N = 256;  Ntot = 256;  rowoff = 0;   tpl = 256; }
    const int l = bid / tpl, tt = bid % tpl;
    const int nt = N / 32;
    const int n0 = (tt % nt) * 32, k0 = (tt / nt) * 32;

    const float* Wl = W + (size_t)l * K * N;
    t[threadIdx.y][threadIdx.x] = Wl[(size_t)(k0 + threadIdx.y) * N + n0 + threadIdx.x];
    __syncthreads();
    const size_t o = ((size_t)l * Ntot + rowoff + n0 + threadIdx.y) * K + k0 + threadIdx.x;
    hi[o] = __float2half_rn(t[threadIdx.x][threadIdx.y]);
}

__global__ void bpack_kernel(const float* __restrict__ bo, const float* __restrict__ ba,
                             float* __restrict__ boa)
{
    const int l = blockIdx.x, t = threadIdx.x;   // 384 threads
    boa[l * 384 + t] = (t < 256) ? bo[l * 256 + t] : ba[l * 128 + (t - 256)];
}

// ---------------- pipelined fp16 mma.sync GEMM core (single pass) ----------------
// C = A[M,K] @ B[N,K]^T + bias. CTA 128x128, 8 warps 2x4, warp tile 64x32,
// BK=32, cp.async 4-stage pipeline.
#define GPITCH 80
#define TILESZ 10240
#define STGSZ  20480   // A + B
#define NSTG   4

__device__ __forceinline__ void gemm_core(
    const f16* __restrict__ A, const f16* __restrict__ B,
    const float* __restrict__ bias, float* __restrict__ Cf,
    f16* __restrict__ Ch,
    int K, int N, int mode, int m0, int n0, uint8_t* sm)
{
    const uint32_t sb = smem_u32(sm);
    const int tid = threadIdx.x;
    const int wid = tid >> 5, lane = tid & 31;
    const int wm = wid >> 2, wn = wid & 3;
    const int m0w = wm * 64, n0w = wn * 32;
    const int tlq = lane >> 3, rlq = lane & 7;

    const f16* gA = A + (size_t)m0 * K;
    const f16* gB = B + (size_t)n0 * K;

    float acc[4][4][4];
#pragma unroll
    for (int i = 0; i < 4; i++)
#pragma unroll
        for (int j = 0; j < 4; j++)
#pragma unroll
            for (int c = 0; c < 4; c++) acc[i][j][c] = 0.f;

    const int nchunk = K >> 5;

    auto docopy = [&](int ch) {
        const int k0 = ch << 5;
        const uint32_t sbase = sb + (uint32_t)(ch % NSTG) * STGSZ;
#pragma unroll
        for (int j = 0; j < 4; j++) {
            const int buf = j >> 1;                  // 0=A, 1=B
            const int s = tid + ((j & 1) << 8);
            const int row = s >> 2, seg = s & 3;
            const f16* g = (buf ? gB : gA) + (size_t)row * K + k0 + seg * 8;
            const uint32_t d = sbase + buf * TILESZ + row * GPITCH + seg * 16;
            CP_ASYNC16(d, g);
        }
        CP_COMMIT();
    };

    for (int p = 0; p < NSTG - 1 && p < nchunk; p++) docopy(p);
    for (int ch = 0; ch < nchunk; ch++) {
        if (ch + NSTG - 1 < nchunk) { docopy(ch + NSTG - 1); CP_WAIT(NSTG - 1); }
        else if (ch + 1 < nchunk)   { CP_WAIT(1); }   // conservative tail
        else                        { CP_WAIT(0); }
        __syncthreads();

        const uint32_t soff = sb + (uint32_t)(ch % NSTG) * STGSZ;
#pragma unroll
        for (int ks = 0; ks < 2; ks++) {
            const int kk = ks * 16;
            uint32_t af[16], bfr[8];

#pragma unroll
            for (int mi = 0; mi < 4; mi++) {
                const int r = m0w + mi * 16 + rlq + ((tlq & 1) << 3);
                const int kc = kk + ((tlq >> 1) << 3);
                ldm4(af + mi * 4, soff + r * GPITCH + kc * 2);
            }
#pragma unroll
            for (int nj = 0; nj < 2; nj++) {
                const int r = n0w + nj * 16 + rlq + ((tlq >> 1) << 3);
                const int kc = kk + ((tlq & 1) << 3);
                ldm4(bfr + nj * 4, soff + TILESZ + r * GPITCH + kc * 2);
            }
#pragma unroll
            for (int mi = 0; mi < 4; mi++)
#pragma unroll
                for (int ni = 0; ni < 4; ni++) {
                    uint32_t b2r[2] = {bfr[(ni >> 1) * 4 + (ni & 1) * 2],
                                       bfr[(ni >> 1) * 4 + (ni & 1) * 2 + 1]};
                    mma16816(acc[mi][ni], af + mi * 4, b2r);
                }
        }
        __syncthreads();
    }

    const int g = lane >> 2, tg = lane & 3;
#pragma unroll
    for (int mi = 0; mi < 4; mi++) {
        const int r0 = m0 + m0w + mi * 16 + g;
#pragma unroll
        for (int ni = 0; ni < 4; ni++) {
            const int col = n0 + n0w + ni * 8 + tg * 2;
            const float b0 = bias[col], b1 = bias[col + 1];
            float v00 = acc[mi][ni][0] + b0, v01 = acc[mi][ni][1] + b1;
            float v10 = acc[mi][ni][2] + b0, v11 = acc[mi][ni][3] + b1;
            if (mode == 0) {
                *(float2*)(Cf + (size_t)r0 * N + col)       = make_float2(v00, v01);
                *(float2*)(Cf + (size_t)(r0 + 8) * N + col) = make_float2(v10, v11);
            } else {
                v00 = fmaxf(v00, 0.f); v01 = fmaxf(v01, 0.f);
                v10 = fmaxf(v10, 0.f); v11 = fmaxf(v11, 0.f);
                *(uint32_t*)(Ch + (size_t)r0 * N + col) =
                    h2u(__halves2half2(__float2half_rn(v00), __float2half_rn(v01)));
                *(uint32_t*)(Ch + (size_t)(r0 + 8) * N + col) =
                    h2u(__halves2half2(__float2half_rn(v10), __float2half_rn(v11)));
            }
        }
    }
}

__global__ void __launch_bounds__(256, 2) mma_gemm(
    const f16* __restrict__ A, const f16* __restrict__ B,
    const float* __restrict__ bias, float* __restrict__ Cf,
    f16* __restrict__ Ch, int K, int N, int mode)
{
    extern __shared__ __align__(16) uint8_t sm[];
    gemm_core(A, B, bias, Cf, Ch, K, N, mode,
              blockIdx.y * 128, blockIdx.x * 128, sm);
}

// fused value + offsets/logits projections (independent, share a launch)
// grid.x: 0-1 = value tiles (N=256), 2-4 = proj tiles (N=384)
__global__ void __launch_bounds__(256, 2) proj_gemm(
    const f16* __restrict__ xh, const f16* __restrict__ wvh,
    const float* __restrict__ bv, float* __restrict__ vb,
    const f16* __restrict__ qh, const f16* __restrict__ woah,
    const float* __restrict__ boa, float* __restrict__ ob)
{
    extern __shared__ __align__(16) uint8_t sm[];
    const int m0 = blockIdx.y * 128;
    if (blockIdx.x < 2) {
        gemm_core(xh, wvh, bv, vb, nullptr, 256, 256, 0, m0, blockIdx.x * 128, sm);
    } else {
        gemm_core(qh, woah, boa, ob, nullptr, 256, 384, 0, m0,
                  (blockIdx.x - 2) * 128, sm);
    }
}

// ---------------- non-GEMM kernels ----------------
__device__ __forceinline__ float warp_sum(float v) {
#pragma unroll
    for (int o = 16; o > 0; o >>= 1) v += __shfl_xor_sync(0xffffffffu, v, o);
    return v;
}
__device__ __forceinline__ float half_sum16(float v) {
#pragma unroll
    for (int o = 8; o > 0; o >>= 1) v += __shfl_xor_sync(0xffffffffu, v, o);
    return v;
}
__device__ __forceinline__ float half_max16(float v) {
#pragma unroll
    for (int o = 8; o > 0; o >>= 1) v = fmaxf(v, __shfl_xor_sync(0xffffffffu, v, o));
    return v;
}

// flatten: (B,D,H,W) -> x fp32, pos fp32, x fp16, q=x+pos fp16
__global__ void flatten_kernel(const float* __restrict__ s0, const float* __restrict__ s1,
                               const float* __restrict__ s2, const float* __restrict__ s3,
                               const float* __restrict__ p0, const float* __restrict__ p1,
                               const float* __restrict__ p2, const float* __restrict__ p3,
                               const float* __restrict__ lenc,
                               float* __restrict__ x, float* __restrict__ pos,
                               f16* __restrict__ xh, f16* __restrict__ qh)
{
    __shared__ float ts[32][33];
    __shared__ float tp[32][33];
    const int b  = blockIdx.z;
    const int q0 = blockIdx.x * 32;
    const int d0 = blockIdx.y * 32;

    int l, start, HW;
    const float *src, *pp;
    if (q0 < 4096)      { l = 0; start = 0;    HW = 4096; src = s0; pp = p0; }
    else if (q0 < 5120) { l = 1; start = 4096; HW = 1024; src = s1; pp = p1; }
    else if (q0 < 5376) { l = 2; start = 5120; HW = 256;  src = s2; pp = p2; }
    else                { l = 3; start = 5376; HW = 64;   src = s3; pp = p3; }

    const int pix0 = q0 - start;
    const int tx = threadIdx.x, ty = threadIdx.y;

    long sidx = ((long)b * DMODEL + (d0 + ty)) * HW + pix0 + tx;
    ts[ty][tx] = src[sidx];
    tp[ty][tx] = pp[sidx];
    __syncthreads();

    const int q  = q0 + ty;
    const int dd = d0 + tx;
    const size_t oidx = ((size_t)b * LQ + q) * DMODEL + dd;
    const float xv = ts[tx][ty];
    const float pv = tp[tx][ty] + lenc[l * DMODEL + dd];
    x[oidx]   = xv;
    pos[oidx] = pv;
    xh[oidx] = __float2half_rn(xv);
    qh[oidx] = __float2half_rn(xv + pv);
}

// deformable sampling + fused softmax; one warp per (b,q,h)
// tap-parallel: 4 tap-groups x 8 lanes, each lane holds 4 channels (float4)
__global__ void __launch_bounds__(256) sample_kernel(
    const float* __restrict__ val, const float* __restrict__ proj,
    f16* __restrict__ acch)
{
    const int gwid = (blockIdx.x * blockDim.x + threadIdx.x) >> 5;
    const int lane = threadIdx.x & 31;
    const int h = gwid % NH;
    const int q = (gwid / NH) % LQ;
    const int b = gwid / (NH * LQ);

    const size_t rowq = (size_t)b * LQ + q;
    const float* pr = proj + rowq * 384;

    float lv = pr[256 + h * 16 + (lane & 15)];
    float mx = half_max16(lv);
    float e  = __expf(lv - mx);
    float s  = half_sum16(e);
    const float wgt = e / s;

    int W0, start0;
    if (q < 4096)      { W0 = 64; start0 = 0;    }
    else if (q < 5120) { W0 = 32; start0 = 4096; }
    else if (q < 5376) { W0 = 16; start0 = 5120; }
    else               { W0 = 8;  start0 = 5376; }
    const int pix = q - start0;
    const float refx = ((pix % W0) + 0.5f) / (float)W0;
    const float refy = ((pix / W0) + 0.5f) / (float)W0;

    const float* ob = pr + h * 32;
    const int tap = lane >> 3;
    const int tdx = tap & 1, tdy = tap >> 1;
    const int ch4 = (lane & 7) * 4;

    const int Ls[4] = {64, 32, 16, 8};
    const int Ss[4] = {0, 4096, 5120, 5376};
    float4 a4 = make_float4(0.f, 0.f, 0.f, 0.f);

#pragma unroll
    for (int l = 0; l < NLVL; l++) {
        const int   HH = Ls[l];
        const float fH = (float)HH;
        const float* vb = val + ((size_t)b * LQ + Ss[l]) * (NH * DH) + h * DH + ch4;
#pragma unroll
        for (int p = 0; p < NPT; p++) {
            const int si = l * NPT + p;
            const float ox = ob[si * 2];
            const float oy = ob[si * 2 + 1];
            const float aw = __shfl_sync(0xffffffffu, wgt, si);
            const float xx = refx * fH + ox - 0.5f;
            const float yy = refy * fH + oy - 0.5f;
            const float xf = floorf(xx), yf = floorf(yy);
            const float dx = xx - xf, dy = yy - yf;
            const int xi = (int)xf + tdx;
            const int yi = (int)yf + tdy;
            const float wt = (tdx ? dx : 1.f - dx) * (tdy ? dy : 1.f - dy) * aw;
            if (xi >= 0 && xi < HH && yi >= 0 && yi < HH) {
                const float4 v = *(const float4*)(vb + (size_t)(yi * HH + xi) * (NH * DH));
                a4.x += wt * v.x; a4.y += wt * v.y;
                a4.z += wt * v.z; a4.w += wt * v.w;
            }
        }
    }
#pragma unroll
    for (int o = 8; o <= 16; o <<= 1) {
        a4.x += __shfl_xor_sync(0xffffffffu, a4.x, o);
        a4.y += __shfl_xor_sync(0xffffffffu, a4.y, o);
        a4.z += __shfl_xor_sync(0xffffffffu, a4.z, o);
        a4.w += __shfl_xor_sync(0xffffffffu, a4.w, o);
    }
    if (tap == 0) {
        const size_t oi = (rowq * NH + h) * DH + ch4;
        *(uint2*)(acch + oi) = make_uint2(
            h2u(__halves2half2(__float2half_rn(a4.x), __float2half_rn(a4.y))),
            h2u(__halves2half2(__float2half_rn(a4.z), __float2half_rn(a4.w))));
    }
}

// fused residual-add + LayerNorm; optional fp16 out; optional q=out+pos fp16
// flags bit0: write oh; bit1: write qh = fp16(out + pos)
__global__ void __launch_bounds__(256) add_ln_kernel(
    const float* __restrict__ x, const float* __restrict__ r,
    const float* __restrict__ g, const float* __restrict__ bta,
    float* __restrict__ out,
    f16* __restrict__ oh,
    const float* __restrict__ pos, f16* __restrict__ qh,
    int flags)
{
    const int row  = blockIdx.x * 8 + (threadIdx.x >> 5);
    const int lane = threadIdx.x & 31;
    const size_t base = (size_t)row * DMODEL;
    const float* xr = x + base;
    const float* rr = r + base;

    float v[8];
    float sum = 0.f;
#pragma unroll
    for (int k = 0; k < 8; k++) {
        v[k] = xr[lane + 32 * k] + rr[lane + 32 * k];
        sum += v[k];
    }
    sum = warp_sum(sum);
    const float mu = sum * (1.f / 256.f);
    float vs = 0.f;
#pragma unroll
    for (int k = 0; k < 8; k++) { float d = v[k] - mu; vs += d * d; }
    vs = warp_sum(vs) * (1.f / 256.f);
    const float inv = rsqrtf(vs + 1e-5f);
#pragma unroll
    for (int k = 0; k < 8; k++) {
        const int c = lane + 32 * k;
        const float o = (v[k] - mu) * inv * g[c] + bta[c];
        out[base + c] = o;
        if (flags & 1) oh[base + c] = __float2half_rn(o);
        if (flags & 2) qh[base + c] = __float2half_rn(o + pos[base + c]);
    }
}

// ---------------- host orchestration ----------------
#define SMEM_GEMM (NSTG * STGSZ)

static void tcgemm(const f16* A, const f16* B, const float* bias,
                   float* Cf, f16* Ch, int K, int N, int mode)
{
    dim3 grid(N / 128, MROWS / 128);
    mma_gemm<<<grid, 256, SMEM_GEMM>>>(A, B, bias, Cf, Ch, K, N, mode);
}

extern "C" void kernel_launch(void* const* d_in, const int* in_sizes, int n_in,
                              void* d_out, int out_size)
{
    cudaFuncSetAttribute(mma_gemm,  cudaFuncAttributeMaxDynamicSharedMemorySize, SMEM_GEMM);
    cudaFuncSetAttribute(proj_gemm, cudaFuncAttributeMaxDynamicSharedMemorySize, SMEM_GEMM);

    // inputs may arrive interleaved (src0,pos0,src1,pos1,...) per dict order
    const float* src[4];
    const float* pos[4];
    if (in_sizes[1] == in_sizes[0]) {
        for (int i = 0; i < 4; i++) {
            src[i] = (const float*)d_in[2 * i];
            pos[i] = (const float*)d_in[2 * i + 1];
        }
    } else {
        for (int i = 0; i < 4; i++) {
            src[i] = (const float*)d_in[i];
            pos[i] = (const float*)d_in[4 + i];
        }
    }
    const float* lenc  = (const float*)d_in[8];
    const float* Wv    = (const float*)d_in[9];
    const float* bv    = (const float*)d_in[10];
    const float* Wo    = (const float*)d_in[11];
    const float* bo    = (const float*)d_in[12];
    const float* Wa    = (const float*)d_in[13];
    const float* ba    = (const float*)d_in[14];
    const float* Wout  = (const float*)d_in[15];
    const float* bout  = (const float*)d_in[16];
    const float* ln1g  = (const float*)d_in[17];
    const float* ln1b  = (const float*)d_in[18];
    const float* W1    = (const float*)d_in[19];
    const float* b1    = (const float*)d_in[20];
    const float* W2    = (const float*)d_in[21];
    const float* b2    = (const float*)d_in[22];
    const float* ln2g  = (const float*)d_in[23];
    const float* ln2b  = (const float*)d_in[24];
    float* out = (float*)d_out;

    float *x, *posb, *vb, *ob, *tmpb, *boa;
    cudaGetSymbolAddress((void**)&x,    g_x);
    cudaGetSymbolAddress((void**)&posb, g_pos);
    cudaGetSymbolAddress((void**)&vb,   g_val);
    cudaGetSymbolAddress((void**)&ob,   g_off);
    cudaGetSymbolAddress((void**)&tmpb, g_tmp);
    cudaGetSymbolAddress((void**)&boa,  g_boa);

    f16 *xh, *qh, *ach, *hh;
    cudaGetSymbolAddress((void**)&xh,  g_xh);
    cudaGetSymbolAddress((void**)&qh,  g_qh);
    cudaGetSymbolAddress((void**)&ach, g_ach);
    cudaGetSymbolAddress((void**)&hh,  g_hh);

    f16 *wvh, *woah, *wuh, *w1h, *w2h;
    cudaGetSymbolAddress((void**)&wvh,  g_wv_h);
    cudaGetSymbolAddress((void**)&woah, g_woa_h);
    cudaGetSymbolAddress((void**)&wuh,  g_wu_h);
    cudaGetSymbolAddress((void**)&w1h,  g_w1_h);
    cudaGetSymbolAddress((void**)&w2h,  g_w2_h);

    // launch 0: all weight transposes + fp16; launch 1: bias pack
    {
        dim3 blk(32, 32);
        prep_kernel<<<4416, blk>>>(Wv, Wo, Wa, Wout, W1, W2,
                                   wvh, woah, wuh, w1h, w2h);
        bpack_kernel<<<NLAYERS, 384>>>(bo, ba, boa);
    }

    // launch 2: flatten inputs
    {
        dim3 grid(LQ / 32, DMODEL / 32, BATCH);
        dim3 blk(32, 32);
        flatten_kernel<<<grid, blk>>>(src[0], src[1], src[2], src[3],
                                      pos[0], pos[1], pos[2], pos[3],
                                      lenc, x, posb, xh, qh);
    }

    const int sample_blocks = (MROWS * NH * 32) / 256;
    const int ln_blocks = MROWS / 8;

    for (int i = 0; i < NLAYERS; i++) {
        const size_t o64k  = (size_t)i * 256 * 256;
        const size_t o96k  = (size_t)i * 384 * 256;
        const size_t o256k = (size_t)i * 1024 * 256;

        // fused: value = x@Wv + bv  ||  offsets+logits = q@[Wo|Wa] + [bo|ba]
        {
            dim3 grid(5, MROWS / 128);
            proj_gemm<<<grid, 256, SMEM_GEMM>>>(
                xh, wvh + o64k, bv + (size_t)i * 256, vb,
                qh, woah + o96k, boa + (size_t)i * 384, ob);
        }
        // softmax + deformable sampling -> fp16 acc
        sample_kernel<<<sample_blocks, 256>>>(vb, ob, ach);
        // output projection
        tcgemm(ach, wuh + o64k, bout + (size_t)i * 256, tmpb, nullptr, 256, 256, 0);
        // x = LN(x + attn); fp16 for W1
        add_ln_kernel<<<ln_blocks, 256>>>(x, tmpb, ln1g + (size_t)i * 256,
                                          ln1b + (size_t)i * 256, x,
                                          xh, nullptr, nullptr, 1);
        // FFN: h = relu(x @ W1 + b1) -> fp16
        tcgemm(xh, w1h + o256k, b1 + (size_t)i * 1024, nullptr, hh, 256, 1024, 1);
        tcgemm(hh, w2h + o256k, b2 + (size_t)i * 256, tmpb, nullptr, 1024, 256, 0);
        // x = LN(x + ffn); fp16 x for next Wv; q = x + pos fp16 for next layer
        const int last = (i == NLAYERS - 1);
        add_ln_kernel<<<ln_blocks, 256>>>(x, tmpb, ln2g + (size_t)i * 256,
                                          ln2b + (size_t)i * 256,
                                          last ? out : x,
                                          xh, posb, qh, last ? 0 : 3);
    }
}